// round 2
// baseline (speedup 1.0000x reference)
#include <cuda_runtime.h>
#include <math.h>

#define NG 10000      // genes
#define NC 8192       // cells
#define ZD 100        // z dim
#define KD 32         // key dim
#define HD 256        // hidden dim (key MLP)
#define GT 128        // genes per CTA (main)
#define CT 128        // cell tile (main)
#define NSPLIT 16     // cell splits
#define TILES_PER_SPLIT (NC / (CT * NSPLIT))   // 4

typedef unsigned long long u64;

// ---------------- packed f32x2 helpers ----------------
#define FFMA2(d, a, b) asm("fma.rn.f32x2 %0, %1, %2, %0;" : "+l"(d) : "l"(a), "l"(b))
#define FADD2(d, a, b) asm("add.rn.f32x2 %0, %1, %2;" : "=l"(d) : "l"(a), "l"(b))
#define PACK2(out, lo, hi) asm("mov.b64 %0, {%1, %2};" : "=l"(out) : "r"(lo), "r"(hi))
#define UNPACK2(lo, hi, in) asm("mov.b64 {%0, %1}, %2;" : "=r"(lo), "=r"(hi) : "l"(in))

__device__ __forceinline__ float gelu_exact(float x) {
    return 0.5f * x * (1.0f + erff(x * 0.70710678118654752440f));
}

// ---------------- device scratch ----------------
__device__ __align__(16) float g_key[NC * KD];          // [cell][k]
__device__ __align__(16) float g_query[NG * KD];        // [gene][k]
__device__ __align__(16) float g_pnum[NSPLIT * ZD * NG];// [split][z][gene]
__device__ __align__(16) float g_pden[NSPLIT * NG];     // [split][gene]

// ---------------- kernel A: key MLP (cells) ----------------
// key = gelu(raw_Z^T @ Wz1 + bz1) @ Wz2 + bz2   -> (8192, 32)
__global__ void __launch_bounds__(256, 1)
key_mlp_kernel(const float* __restrict__ rawZ,
               const float* __restrict__ Wz1, const float* __restrict__ bz1,
               const float* __restrict__ Wz2, const float* __restrict__ bz2) {
    __shared__ float Zs[ZD * 32];     // [k][cc]
    __shared__ float Hs[32 * HD];     // [cc][h]
    int tid = threadIdx.x;
    int c0 = blockIdx.x * 32;

    for (int idx = tid; idx < ZD * 32; idx += 256) {
        int k = idx >> 5, cc = idx & 31;
        Zs[idx] = rawZ[(size_t)k * NC + c0 + cc];
    }
    __syncthreads();

    {   // each thread owns hidden unit h = tid
        int h = tid;
        float w[ZD];
        #pragma unroll
        for (int k = 0; k < ZD; ++k) w[k] = Wz1[k * HD + h];
        float b = bz1[h];
        for (int cc = 0; cc < 32; ++cc) {
            float a = b;
            #pragma unroll
            for (int k = 0; k < ZD; ++k) a = fmaf(Zs[k * 32 + cc], w[k], a);
            Hs[cc * HD + h] = gelu_exact(a);
        }
    }
    __syncthreads();

    for (int idx = tid; idx < 32 * KD; idx += 256) {
        int cc = idx >> 5, kk = idx & 31;
        float a = bz2[kk];
        #pragma unroll 8
        for (int h = 0; h < HD; ++h) a = fmaf(Hs[cc * HD + h], Wz2[h * KD + kk], a);
        g_key[(size_t)(c0 + cc) * KD + kk] = a;
    }
}

// ---------------- kernel B: query MLP (genes) ----------------
// query = gelu(G_rep @ Wg1 + bg1) @ Wg2 + bg2   -> (10000, 32)
__global__ void query_mlp_kernel(const float* __restrict__ Grep,
                                 const float* __restrict__ Wg1, const float* __restrict__ bg1,
                                 const float* __restrict__ Wg2, const float* __restrict__ bg2) {
    __shared__ float Gs[64 * 101];
    __shared__ float W1s[100 * 32];
    __shared__ float W2s[32 * 32];
    __shared__ float b1s[32], b2s[32];
    int tid = threadIdx.x;
    int g0 = blockIdx.x * 64;
    int valid = min(64, NG - g0);

    for (int idx = tid; idx < valid * 100; idx += 64) {
        int r = idx / 100, c = idx - r * 100;
        Gs[r * 101 + c] = Grep[(size_t)g0 * 100 + idx];
    }
    for (int idx = tid; idx < 100 * 32; idx += 64) W1s[idx] = Wg1[idx];
    for (int idx = tid; idx < 32 * 32; idx += 64) W2s[idx] = Wg2[idx];
    if (tid < 32) { b1s[tid] = bg1[tid]; b2s[tid] = bg2[tid]; }
    __syncthreads();

    if (tid < valid) {
        float hid[32];
        #pragma unroll
        for (int j = 0; j < 32; ++j) hid[j] = b1s[j];
        for (int k = 0; k < 100; ++k) {
            float gv = Gs[tid * 101 + k];
            #pragma unroll
            for (int j = 0; j < 32; ++j) hid[j] = fmaf(gv, W1s[k * 32 + j], hid[j]);
        }
        #pragma unroll
        for (int j = 0; j < 32; ++j) hid[j] = gelu_exact(hid[j]);
        int g = g0 + tid;
        #pragma unroll 4
        for (int kk = 0; kk < 32; ++kk) {
            float a = b2s[kk];
            #pragma unroll
            for (int j = 0; j < 32; ++j) a = fmaf(hid[j], W2s[j * 32 + kk], a);
            g_query[(size_t)g * KD + kk] = a;
        }
    }
}

// ---------------- main fused kernel ----------------
// per thread: one gene. Stream cells; e = exp(q.k/sqrt(32) + gumbel);
// den += e; acc[z] += e * genZ[z][cell].  No max-subtraction needed (logits <~ 19).
__global__ void decoder_main_kernel(const float* __restrict__ gumbel,
                                    const float* __restrict__ genZ) {
    extern __shared__ float smem[];
    float* Ks = smem;              // [j][32]   (CT*KD floats)
    float* Vs = smem + CT * KD;    // [j][100]  (CT*ZD floats)

    int tid = threadIdx.x;
    int g = blockIdx.x * GT + tid;
    int gload = min(g, NG - 1);
    int split = blockIdx.y;

    // load query row into packed regs
    u64 q2[KD / 2];
    {
        const ulonglong2* qp = reinterpret_cast<const ulonglong2*>(g_query + (size_t)gload * KD);
        #pragma unroll
        for (int i = 0; i < KD / 4; ++i) {
            ulonglong2 t = qp[i];
            q2[2 * i] = t.x; q2[2 * i + 1] = t.y;
        }
    }

    u64 acc2[ZD / 2];
    #pragma unroll
    for (int i = 0; i < ZD / 2; ++i) acc2[i] = 0ULL;
    float den = 0.0f;

    for (int t = 0; t < TILES_PER_SPLIT; ++t) {
        int cbase = (split * TILES_PER_SPLIT + t) * CT;
        __syncthreads();
        // stage K tile (contiguous)
        for (int idx = tid; idx < CT * KD; idx += GT)
            Ks[idx] = g_key[(size_t)cbase * KD + idx];
        // stage V tile transposed: Vs[j][z] = genZ[z][cbase+j]
        for (int idx = tid; idx < CT * ZD; idx += GT) {
            int z = idx >> 7, j = idx & (CT - 1);
            Vs[j * ZD + z] = genZ[(size_t)z * NC + cbase + j];
        }
        __syncthreads();

        const float* grow = gumbel + (size_t)gload * NC + cbase;
        float4 gb = *reinterpret_cast<const float4*>(grow);

        #pragma unroll 1
        for (int j0 = 0; j0 < CT; j0 += 4) {
            int jn = (j0 + 4 < CT) ? (j0 + 4) : j0;   // safe prefetch index
            float4 gbn = *reinterpret_cast<const float4*>(grow + jn);
            float gbv[4] = {gb.x, gb.y, gb.z, gb.w};

            #pragma unroll
            for (int jj = 0; jj < 4; ++jj) {
                int j = j0 + jj;
                const ulonglong2* kp = reinterpret_cast<const ulonglong2*>(Ks + j * KD);
                u64 s0 = 0ULL, s1 = 0ULL, s2 = 0ULL, s3 = 0ULL;
                #pragma unroll
                for (int i = 0; i < 4; ++i) {
                    ulonglong2 ka = kp[2 * i];
                    ulonglong2 kb = kp[2 * i + 1];
                    FFMA2(s0, q2[4 * i + 0], ka.x);
                    FFMA2(s1, q2[4 * i + 1], ka.y);
                    FFMA2(s2, q2[4 * i + 2], kb.x);
                    FFMA2(s3, q2[4 * i + 3], kb.y);
                }
                FADD2(s0, s0, s1);
                FADD2(s2, s2, s3);
                FADD2(s0, s0, s2);
                unsigned slo, shi;
                UNPACK2(slo, shi, s0);
                float sdot = __uint_as_float(slo) + __uint_as_float(shi);
                float p = __expf(fmaf(sdot, 0.17677669529663689f, gbv[jj]));
                den += p;
                unsigned pu = __float_as_uint(p);
                u64 p2;
                PACK2(p2, pu, pu);

                const ulonglong2* vp = reinterpret_cast<const ulonglong2*>(Vs + j * ZD);
                #pragma unroll
                for (int i = 0; i < ZD / 4; ++i) {
                    ulonglong2 vv = vp[i];
                    FFMA2(acc2[2 * i], p2, vv.x);
                    FFMA2(acc2[2 * i + 1], p2, vv.y);
                }
            }
            gb = gbn;
        }
    }

    if (g < NG) {
        float* base = g_pnum + (size_t)split * (ZD * NG) + g;
        #pragma unroll
        for (int i = 0; i < ZD / 2; ++i) {
            unsigned lo, hi;
            UNPACK2(lo, hi, acc2[i]);
            base[(size_t)(2 * i) * NG] = __uint_as_float(lo);
            base[(size_t)(2 * i + 1) * NG] = __uint_as_float(hi);
        }
        g_pden[split * NG + g] = den;
    }
}

// ---------------- reduce: sum splits, divide, emit (z, gene) ----------------
__global__ void reduce_kernel(float* __restrict__ out) {
    int idx = blockIdx.x * blockDim.x + threadIdx.x;   // idx = z*NG + g
    if (idx >= ZD * NG) return;
    int gidx = idx % NG;
    float num = 0.0f, d = 0.0f;
    #pragma unroll
    for (int s = 0; s < NSPLIT; ++s) {
        num += g_pnum[(size_t)s * (ZD * NG) + idx];
        d   += g_pden[s * NG + gidx];
    }
    out[idx] = num / d;
}

// ---------------- launch ----------------
extern "C" void kernel_launch(void* const* d_in, const int* in_sizes, int n_in,
                              void* d_out, int out_size) {
    const float* rawZ   = (const float*)d_in[0];
    const float* genZ   = (const float*)d_in[1];
    const float* Grep   = (const float*)d_in[2];
    const float* gumbel = (const float*)d_in[3];
    const float* Wz1 = (const float*)d_in[4];
    const float* bz1 = (const float*)d_in[5];
    const float* Wz2 = (const float*)d_in[6];
    const float* bz2 = (const float*)d_in[7];
    const float* Wg1 = (const float*)d_in[8];
    const float* bg1 = (const float*)d_in[9];
    const float* Wg2 = (const float*)d_in[10];
    const float* bg2 = (const float*)d_in[11];
    float* out = (float*)d_out;

    const int smem_main = (CT * KD + CT * ZD) * sizeof(float);   // 67584 B
    cudaFuncSetAttribute(decoder_main_kernel,
                         cudaFuncAttributeMaxDynamicSharedMemorySize, smem_main);

    key_mlp_kernel<<<NC / 32, 256>>>(rawZ, Wz1, bz1, Wz2, bz2);
    query_mlp_kernel<<<(NG + 63) / 64, 64>>>(Grep, Wg1, bg1, Wg2, bg2);

    dim3 grid((NG + GT - 1) / GT, NSPLIT);
    decoder_main_kernel<<<grid, GT, smem_main>>>(gumbel, genZ);

    reduce_kernel<<<(ZD * NG + 255) / 256, 256>>>(out);
}

// round 3
// speedup vs baseline: 1.2030x; 1.2030x over previous
#include <cuda_runtime.h>
#include <math.h>

#define NG 10000      // genes
#define NC 8192       // cells
#define ZD 100        // z dim
#define KD 32         // key dim
#define HD 256        // hidden dim (key MLP)
#define GT 128        // genes per CTA
#define NSPLIT 16     // cell splits
#define CPS (NC / NSPLIT)       // 512 cells per split
#define SC 64         // cell subtile
#define NSUB (CPS / SC)         // 8 subtiles
#define ZP 108        // padded V row (floats): 4-aligned, 108%32=12 -> only 4-way STS conflict
#define ZT 28         // z span per thread (4 thread-groups * 28 = 112 >= 100)

typedef unsigned long long u64;

// ---------------- packed f32x2 helpers ----------------
#define FFMA2(d, a, b) asm("fma.rn.f32x2 %0, %1, %2, %0;" : "+l"(d) : "l"(a), "l"(b))
#define FADD2(d, a, b) asm("add.rn.f32x2 %0, %1, %2;" : "=l"(d) : "l"(a), "l"(b))
#define PACK2(out, lo, hi) asm("mov.b64 %0, {%1, %2};" : "=l"(out) : "r"(lo), "r"(hi))
#define UNPACK2(lo, hi, in) asm("mov.b64 {%0, %1}, %2;" : "=r"(lo), "=r"(hi) : "l"(in))

__device__ __forceinline__ float gelu_exact(float x) {
    return 0.5f * x * (1.0f + erff(x * 0.70710678118654752440f));
}

// ---------------- device scratch ----------------
__device__ __align__(16) float g_key[NC * KD];           // [cell][k]
__device__ __align__(16) float g_query[NG * KD];         // [gene][k]
__device__ __align__(16) float g_pnum[NSPLIT * ZD * NG]; // [split][z][gene]
__device__ __align__(16) float g_pden[NSPLIT * NG];      // [split][gene]

// ---------------- kernel A: key MLP (cells) ----------------
__global__ void __launch_bounds__(256, 1)
key_mlp_kernel(const float* __restrict__ rawZ,
               const float* __restrict__ Wz1, const float* __restrict__ bz1,
               const float* __restrict__ Wz2, const float* __restrict__ bz2) {
    __shared__ float Zs[ZD * 32];     // [k][cc]
    __shared__ float Hs[32 * HD];     // [cc][h]
    int tid = threadIdx.x;
    int c0 = blockIdx.x * 32;

    for (int idx = tid; idx < ZD * 32; idx += 256) {
        int k = idx >> 5, cc = idx & 31;
        Zs[idx] = rawZ[(size_t)k * NC + c0 + cc];
    }
    __syncthreads();

    {   // each thread owns hidden unit h = tid
        int h = tid;
        float w[ZD];
        #pragma unroll
        for (int k = 0; k < ZD; ++k) w[k] = Wz1[k * HD + h];
        float b = bz1[h];
        for (int cc = 0; cc < 32; ++cc) {
            float a = b;
            #pragma unroll
            for (int k = 0; k < ZD; ++k) a = fmaf(Zs[k * 32 + cc], w[k], a);
            Hs[cc * HD + h] = gelu_exact(a);
        }
    }
    __syncthreads();

    for (int idx = tid; idx < 32 * KD; idx += 256) {
        int cc = idx >> 5, kk = idx & 31;
        float a = bz2[kk];
        #pragma unroll 8
        for (int h = 0; h < HD; ++h) a = fmaf(Hs[cc * HD + h], Wz2[h * KD + kk], a);
        g_key[(size_t)(c0 + cc) * KD + kk] = a;
    }
}

// ---------------- kernel B: query MLP (genes) ----------------
__global__ void query_mlp_kernel(const float* __restrict__ Grep,
                                 const float* __restrict__ Wg1, const float* __restrict__ bg1,
                                 const float* __restrict__ Wg2, const float* __restrict__ bg2) {
    __shared__ float Gs[64 * 101];
    __shared__ float W1s[100 * 32];
    __shared__ float W2s[32 * 32];
    __shared__ float b1s[32], b2s[32];
    int tid = threadIdx.x;
    int g0 = blockIdx.x * 64;
    int valid = min(64, NG - g0);

    for (int idx = tid; idx < valid * 100; idx += 64) {
        int r = idx / 100, c = idx - r * 100;
        Gs[r * 101 + c] = Grep[(size_t)g0 * 100 + idx];
    }
    for (int idx = tid; idx < 100 * 32; idx += 64) W1s[idx] = Wg1[idx];
    for (int idx = tid; idx < 32 * 32; idx += 64) W2s[idx] = Wg2[idx];
    if (tid < 32) { b1s[tid] = bg1[tid]; b2s[tid] = bg2[tid]; }
    __syncthreads();

    if (tid < valid) {
        float hid[32];
        #pragma unroll
        for (int j = 0; j < 32; ++j) hid[j] = b1s[j];
        for (int k = 0; k < 100; ++k) {
            float gv = Gs[tid * 101 + k];
            #pragma unroll
            for (int j = 0; j < 32; ++j) hid[j] = fmaf(gv, W1s[k * 32 + j], hid[j]);
        }
        #pragma unroll
        for (int j = 0; j < 32; ++j) hid[j] = gelu_exact(hid[j]);
        int g = g0 + tid;
        #pragma unroll 4
        for (int kk = 0; kk < 32; ++kk) {
            float a = b2s[kk];
            #pragma unroll
            for (int j = 0; j < 32; ++j) a = fmaf(hid[j], W2s[j * 32 + kk], a);
            g_query[(size_t)g * KD + kk] = a;
        }
    }
}

// ---------------- main fused kernel ----------------
// Phase A (thread = gene): p = exp(q.k/sqrt32 + gumbel) -> Ps smem, den += p.
// Phase B (thread = 4 genes x 28 z): register-tiled PV outer product.
__global__ void __launch_bounds__(GT, 2)
decoder_main_kernel(const float* __restrict__ gumbel,
                    const float* __restrict__ genZ) {
    extern __shared__ float smem[];
    float* Ks = smem;                          // [c][32]   : SC*KD
    float* Vs = smem + SC * KD;                // [c][ZP]   : SC*ZP
    float* Ps = smem + SC * KD + SC * ZP;      // [c][GT]   : SC*GT

    int tid = threadIdx.x;
    int g = blockIdx.x * GT + tid;             // phase-A gene
    int gload = min(g, NG - 1);
    int split = blockIdx.y;

    // phase-B tile coords
    int gx = tid & 31;                         // gene group (4 genes)
    int zy = tid >> 5;                         // z group (28 z)

    // query row (phase A) in packed regs
    u64 q2[KD / 2];
    {
        const ulonglong2* qp = reinterpret_cast<const ulonglong2*>(g_query + (size_t)gload * KD);
        #pragma unroll
        for (int i = 0; i < KD / 4; ++i) {
            ulonglong2 t = qp[i];
            q2[2 * i] = t.x; q2[2 * i + 1] = t.y;
        }
    }

    u64 acc[4][ZT / 2];                        // 4 genes x 14 z-pairs
    #pragma unroll
    for (int gg = 0; gg < 4; ++gg)
        #pragma unroll
        for (int i = 0; i < ZT / 2; ++i) acc[gg][i] = 0ULL;
    float den = 0.0f;

    for (int t = 0; t < NSUB; ++t) {
        int cbase = split * CPS + t * SC;
        __syncthreads();   // protect Ks/Vs/Ps from previous iteration's readers

        // stage K tile: SC*KD floats, contiguous
        {
            const float4* src = reinterpret_cast<const float4*>(g_key + (size_t)cbase * KD);
            float4* dst = reinterpret_cast<float4*>(Ks);
            #pragma unroll
            for (int i = 0; i < (SC * KD / 4) / GT; ++i)
                dst[tid + i * GT] = src[tid + i * GT];
        }
        // stage V tile transposed: Vs[c*ZP + z] = genZ[z][cbase+c]
        for (int idx = tid; idx < SC * ZD; idx += GT) {
            int z = idx / SC, c = idx - z * SC;
            Vs[c * ZP + z] = genZ[(size_t)z * NC + cbase + c];
        }
        __syncthreads();

        // ---- Phase A: p for SC cells ----
        {
            const float* grow = gumbel + (size_t)gload * NC + cbase;
            float4 gb = *reinterpret_cast<const float4*>(grow);
            #pragma unroll 1
            for (int c0 = 0; c0 < SC; c0 += 4) {
                int cn = (c0 + 4 < SC) ? (c0 + 4) : c0;
                float4 gbn = *reinterpret_cast<const float4*>(grow + cn);
                float gbv[4] = {gb.x, gb.y, gb.z, gb.w};
                #pragma unroll
                for (int jj = 0; jj < 4; ++jj) {
                    int c = c0 + jj;
                    const ulonglong2* kp = reinterpret_cast<const ulonglong2*>(Ks + c * KD);
                    u64 s0 = 0ULL, s1 = 0ULL, s2 = 0ULL, s3 = 0ULL;
                    #pragma unroll
                    for (int i = 0; i < 4; ++i) {
                        ulonglong2 ka = kp[2 * i];
                        ulonglong2 kb = kp[2 * i + 1];
                        FFMA2(s0, q2[4 * i + 0], ka.x);
                        FFMA2(s1, q2[4 * i + 1], ka.y);
                        FFMA2(s2, q2[4 * i + 2], kb.x);
                        FFMA2(s3, q2[4 * i + 3], kb.y);
                    }
                    FADD2(s0, s0, s1);
                    FADD2(s2, s2, s3);
                    FADD2(s0, s0, s2);
                    unsigned slo, shi;
                    UNPACK2(slo, shi, s0);
                    float sdot = __uint_as_float(slo) + __uint_as_float(shi);
                    float p = __expf(fmaf(sdot, 0.17677669529663689f, gbv[jj]));
                    den += p;
                    Ps[c * GT + tid] = p;
                }
                gb = gbn;
            }
        }
        __syncthreads();

        // ---- Phase B: PV register-tiled outer product ----
        #pragma unroll 2
        for (int c = 0; c < SC; ++c) {
            float4 p4 = *reinterpret_cast<const float4*>(Ps + c * GT + gx * 4);
            const ulonglong2* vp = reinterpret_cast<const ulonglong2*>(Vs + c * ZP + zy * ZT);
            u64 v2[ZT / 2];
            #pragma unroll
            for (int i = 0; i < ZT / 4; ++i) {
                ulonglong2 vt = vp[i];
                v2[2 * i] = vt.x; v2[2 * i + 1] = vt.y;
            }
            u64 p2[4];
            {
                unsigned pu0 = __float_as_uint(p4.x), pu1 = __float_as_uint(p4.y);
                unsigned pu2 = __float_as_uint(p4.z), pu3 = __float_as_uint(p4.w);
                PACK2(p2[0], pu0, pu0);
                PACK2(p2[1], pu1, pu1);
                PACK2(p2[2], pu2, pu2);
                PACK2(p2[3], pu3, pu3);
            }
            #pragma unroll
            for (int gg = 0; gg < 4; ++gg)
                #pragma unroll
                for (int i = 0; i < ZT / 2; ++i)
                    FFMA2(acc[gg][i], p2[gg], v2[i]);
        }
    }

    // store den (phase-A ownership)
    if (g < NG) g_pden[split * NG + g] = den;

    // store acc (phase-B ownership): gene = blk*GT + gx*4+gg, z = zy*ZT + 2i(+1)
    {
        int gbase = blockIdx.x * GT + gx * 4;
        float* pbase = g_pnum + (size_t)split * (ZD * NG);
        #pragma unroll
        for (int gg = 0; gg < 4; ++gg) {
            int gene = gbase + gg;
            if (gene < NG) {
                #pragma unroll
                for (int i = 0; i < ZT / 2; ++i) {
                    unsigned lo, hi;
                    UNPACK2(lo, hi, acc[gg][i]);
                    int z0 = zy * ZT + 2 * i;
                    if (z0 < ZD)     pbase[(size_t)z0 * NG + gene] = __uint_as_float(lo);
                    if (z0 + 1 < ZD) pbase[(size_t)(z0 + 1) * NG + gene] = __uint_as_float(hi);
                }
            }
        }
    }
}

// ---------------- reduce: sum splits, divide, emit (z, gene) ----------------
__global__ void reduce_kernel(float* __restrict__ out) {
    int i4 = blockIdx.x * blockDim.x + threadIdx.x;   // one float4
    int base = i4 * 4;
    if (base >= ZD * NG) return;
    int gidx = base % NG;                              // NG%4==0 -> row-aligned
    float4 num = make_float4(0.f, 0.f, 0.f, 0.f);
    float4 den = make_float4(0.f, 0.f, 0.f, 0.f);
    #pragma unroll
    for (int s = 0; s < NSPLIT; ++s) {
        float4 n = *reinterpret_cast<const float4*>(g_pnum + (size_t)s * (ZD * NG) + base);
        float4 d = *reinterpret_cast<const float4*>(g_pden + s * NG + gidx);
        num.x += n.x; num.y += n.y; num.z += n.z; num.w += n.w;
        den.x += d.x; den.y += d.y; den.z += d.z; den.w += d.w;
    }
    float4 o;
    o.x = num.x / den.x; o.y = num.y / den.y; o.z = num.z / den.z; o.w = num.w / den.w;
    *reinterpret_cast<float4*>(out + base) = o;
}

// ---------------- launch ----------------
extern "C" void kernel_launch(void* const* d_in, const int* in_sizes, int n_in,
                              void* d_out, int out_size) {
    const float* rawZ   = (const float*)d_in[0];
    const float* genZ   = (const float*)d_in[1];
    const float* Grep   = (const float*)d_in[2];
    const float* gumbel = (const float*)d_in[3];
    const float* Wz1 = (const float*)d_in[4];
    const float* bz1 = (const float*)d_in[5];
    const float* Wz2 = (const float*)d_in[6];
    const float* bz2 = (const float*)d_in[7];
    const float* Wg1 = (const float*)d_in[8];
    const float* bg1 = (const float*)d_in[9];
    const float* Wg2 = (const float*)d_in[10];
    const float* bg2 = (const float*)d_in[11];
    float* out = (float*)d_out;

    const int smem_main = (SC * KD + SC * ZP + SC * GT) * sizeof(float);  // 68608 B
    cudaFuncSetAttribute(decoder_main_kernel,
                         cudaFuncAttributeMaxDynamicSharedMemorySize, smem_main);

    key_mlp_kernel<<<NC / 32, 256>>>(rawZ, Wz1, bz1, Wz2, bz2);
    query_mlp_kernel<<<(NG + 63) / 64, 64>>>(Grep, Wg1, bg1, Wg2, bg2);

    dim3 grid((NG + GT - 1) / GT, NSPLIT);
    decoder_main_kernel<<<grid, GT, smem_main>>>(gumbel, genZ);

    reduce_kernel<<<(ZD * NG / 4 + 255) / 256, 256>>>(out);
}

// round 5
// speedup vs baseline: 1.2292x; 1.0218x over previous
#include <cuda_runtime.h>
#include <math.h>
#include <stdint.h>

#define NG 10000      // genes
#define NC 8192       // cells
#define ZD 100        // z dim
#define KD 32         // key dim
#define HD 256        // hidden dim (key MLP)
#define GT 128        // genes per CTA (= M)
#define CT 128        // cells per chunk (= K of PV mma)
#define NSPLIT 8      // cell splits
#define CPC (NC / NSPLIT)        // 1024 cells per CTA
#define NCHUNK (CPC / CT)        // 8 chunks
#define NEXT 104      // N of PV mma (100 z + ones row + pad)
#define NT 13         // n8 tiles
#define THREADS 256
#define PSTRIDE 136   // Ps row stride (floats): STS + A-frag conflict-free
#define VSTRIDE 105   // Vs row stride (floats): odd -> STS conflict-free

typedef unsigned long long u64;

// ---------------- packed f32x2 helpers ----------------
#define FFMA2(d, a, b) asm("fma.rn.f32x2 %0, %1, %2, %0;" : "+l"(d) : "l"(a), "l"(b))
#define FADD2(d, a, b) asm("add.rn.f32x2 %0, %1, %2;" : "=l"(d) : "l"(a), "l"(b))
#define UNPACK2(lo, hi, in) asm("mov.b64 {%0, %1}, %2;" : "=r"(lo), "=r"(hi) : "l"(in))

__device__ __forceinline__ float to_tf32(float x) {
    uint32_t r;
    asm("cvt.rna.tf32.f32 %0, %1;" : "=r"(r) : "f"(x));
    return __uint_as_float(r);
}

// m16n8k8 tf32 mma, C=D accum
__device__ __forceinline__ void mma_tf32(float* c,
                                         uint32_t a0, uint32_t a1, uint32_t a2, uint32_t a3,
                                         uint32_t b0, uint32_t b1) {
    asm volatile(
        "mma.sync.aligned.m16n8k8.row.col.f32.tf32.tf32.f32 "
        "{%0,%1,%2,%3}, {%4,%5,%6,%7}, {%8,%9}, {%0,%1,%2,%3};"
        : "+f"(c[0]), "+f"(c[1]), "+f"(c[2]), "+f"(c[3])
        : "r"(a0), "r"(a1), "r"(a2), "r"(a3), "r"(b0), "r"(b1));
}

__device__ __forceinline__ float gelu_exact(float x) {
    return 0.5f * x * (1.0f + erff(x * 0.70710678118654752440f));
}

// ---------------- device scratch ----------------
__device__ __align__(16) float g_key[NC * KD];           // [cell][k]
__device__ __align__(16) float g_query[NG * KD];         // [gene][k]
__device__ __align__(16) float g_pnum[NSPLIT * ZD * NG]; // [split][z][gene]
__device__ __align__(16) float g_pden[NSPLIT * NG];      // [split][gene]

// ---------------- kernel A: key MLP (cells) ----------------
__global__ void __launch_bounds__(256, 1)
key_mlp_kernel(const float* __restrict__ rawZ,
               const float* __restrict__ Wz1, const float* __restrict__ bz1,
               const float* __restrict__ Wz2, const float* __restrict__ bz2) {
    __shared__ float Zs[ZD * 32];
    __shared__ float Hs[32 * HD];
    int tid = threadIdx.x;
    int c0 = blockIdx.x * 32;

    for (int idx = tid; idx < ZD * 32; idx += 256) {
        int k = idx >> 5, cc = idx & 31;
        Zs[idx] = rawZ[(size_t)k * NC + c0 + cc];
    }
    __syncthreads();
    {
        int h = tid;
        float w[ZD];
        #pragma unroll
        for (int k = 0; k < ZD; ++k) w[k] = Wz1[k * HD + h];
        float b = bz1[h];
        for (int cc = 0; cc < 32; ++cc) {
            float a = b;
            #pragma unroll
            for (int k = 0; k < ZD; ++k) a = fmaf(Zs[k * 32 + cc], w[k], a);
            Hs[cc * HD + h] = gelu_exact(a);
        }
    }
    __syncthreads();
    for (int idx = tid; idx < 32 * KD; idx += 256) {
        int cc = idx >> 5, kk = idx & 31;
        float a = bz2[kk];
        #pragma unroll 8
        for (int h = 0; h < HD; ++h) a = fmaf(Hs[cc * HD + h], Wz2[h * KD + kk], a);
        g_key[(size_t)(c0 + cc) * KD + kk] = a;
    }
}

// ---------------- kernel B: query MLP (genes) ----------------
__global__ void query_mlp_kernel(const float* __restrict__ Grep,
                                 const float* __restrict__ Wg1, const float* __restrict__ bg1,
                                 const float* __restrict__ Wg2, const float* __restrict__ bg2) {
    __shared__ float Gs[64 * 101];
    __shared__ float W1s[100 * 32];
    __shared__ float W2s[32 * 32];
    __shared__ float b1s[32], b2s[32];
    int tid = threadIdx.x;
    int g0 = blockIdx.x * 64;
    int valid = min(64, NG - g0);

    for (int idx = tid; idx < valid * 100; idx += 64) {
        int r = idx / 100, c = idx - r * 100;
        Gs[r * 101 + c] = Grep[(size_t)g0 * 100 + idx];
    }
    for (int idx = tid; idx < 100 * 32; idx += 64) W1s[idx] = Wg1[idx];
    for (int idx = tid; idx < 32 * 32; idx += 64) W2s[idx] = Wg2[idx];
    if (tid < 32) { b1s[tid] = bg1[tid]; b2s[tid] = bg2[tid]; }
    __syncthreads();

    if (tid < valid) {
        float hid[32];
        #pragma unroll
        for (int j = 0; j < 32; ++j) hid[j] = b1s[j];
        for (int k = 0; k < 100; ++k) {
            float gv = Gs[tid * 101 + k];
            #pragma unroll
            for (int j = 0; j < 32; ++j) hid[j] = fmaf(gv, W1s[k * 32 + j], hid[j]);
        }
        #pragma unroll
        for (int j = 0; j < 32; ++j) hid[j] = gelu_exact(hid[j]);
        int g = g0 + tid;
        #pragma unroll 4
        for (int kk = 0; kk < 32; ++kk) {
            float a = b2s[kk];
            #pragma unroll
            for (int j = 0; j < 32; ++j) a = fmaf(hid[j], W2s[j * 32 + kk], a);
            g_query[(size_t)g * KD + kk] = a;
        }
    }
}

// ---------------- main fused kernel ----------------
// smem (floats): Ps[CT][PSTRIDE] @0, Vs[CT][VSTRIDE] @17408, Ks[CT][KD] @30848
#define PS_OFF 0
#define VS_OFF (CT * PSTRIDE)                    // 17408
#define KS_OFF (VS_OFF + CT * VSTRIDE)           // 30848
#define SMEM_FLOATS (KS_OFF + CT * KD)           // 34944
#define SMEM_MAIN (SMEM_FLOATS * 4)              // 139776 B

__global__ void __launch_bounds__(THREADS, 1)
decoder_main_kernel(const float* __restrict__ gumbel,
                    const float* __restrict__ genZ) {
    extern __shared__ float smem[];
    float* Ps = smem + PS_OFF;
    float* Vs = smem + VS_OFF;
    float* Ks = smem + KS_OFF;

    int tid = threadIdx.x;
    int wid = tid >> 5;
    int lane = tid & 31;
    int split = blockIdx.y;

    // phase-A identity: gene + cell-half
    int gene = tid & (GT - 1);
    int half = tid >> 7;
    int g = blockIdx.x * GT + gene;
    int gload = min(g, NG - 1);

    // phase-B identity
    int m0 = wid * 16;
    int arow = m0 + (lane >> 2);    // gene row within CTA (A/D frag, low half)
    int acol = lane & 3;            // k offset
    int bn = lane >> 2;             // n offset
    int bk = lane & 3;              // k offset

    // query row in packed regs (exact fp32)
    u64 q2[KD / 2];
    {
        const ulonglong2* qp = reinterpret_cast<const ulonglong2*>(g_query + (size_t)gload * KD);
        #pragma unroll
        for (int i = 0; i < KD / 4; ++i) {
            ulonglong2 t = qp[i];
            q2[2 * i] = t.x; q2[2 * i + 1] = t.y;
        }
    }

    float acc[NT][4];
    #pragma unroll
    for (int nt = 0; nt < NT; ++nt) {
        acc[nt][0] = 0.f; acc[nt][1] = 0.f; acc[nt][2] = 0.f; acc[nt][3] = 0.f;
    }

    for (int t = 0; t < NCHUNK; ++t) {
        int cbase = split * CPC + t * CT;
        __syncthreads();   // protect smem reuse from previous phase B

        // ---- stage V_ext (tf32, [cell][z] stride 105) ----
        for (int idx = tid; idx < NEXT * CT; idx += THREADS) {
            int z = idx >> 7, c = idx & (CT - 1);
            float v;
            if (z < ZD)       v = genZ[(size_t)z * NC + cbase + c];
            else if (z == ZD) v = 1.0f;     // ones row -> denominator
            else              v = 0.0f;
            Vs[c * VSTRIDE + z] = to_tf32(v);
        }
        // ---- stage K tile (contiguous) ----
        {
            const float4* src = reinterpret_cast<const float4*>(g_key + (size_t)cbase * KD);
            float4* dst = reinterpret_cast<float4*>(Ks);
            #pragma unroll
            for (int i = 0; i < (CT * KD / 4) / THREADS; ++i)
                dst[tid + i * THREADS] = src[tid + i * THREADS];
        }
        __syncthreads();

        // ---- phase A: p for this thread's 64 cells -> Ps (tf32 bits) ----
        {
            const float* grow = gumbel + (size_t)gload * NC + cbase + half * 64;
            float4 gb = *reinterpret_cast<const float4*>(grow);
            #pragma unroll 1
            for (int c0 = 0; c0 < 64; c0 += 4) {
                int cn = (c0 + 4 < 64) ? (c0 + 4) : c0;
                float4 gbn = *reinterpret_cast<const float4*>(grow + cn);
                float gbv[4] = {gb.x, gb.y, gb.z, gb.w};
                #pragma unroll
                for (int jj = 0; jj < 4; ++jj) {
                    int c = half * 64 + c0 + jj;
                    const ulonglong2* kp = reinterpret_cast<const ulonglong2*>(Ks + c * KD);
                    u64 s0 = 0ULL, s1 = 0ULL, s2 = 0ULL, s3 = 0ULL;
                    #pragma unroll
                    for (int i = 0; i < 4; ++i) {
                        ulonglong2 ka = kp[2 * i];
                        ulonglong2 kb = kp[2 * i + 1];
                        FFMA2(s0, q2[4 * i + 0], ka.x);
                        FFMA2(s1, q2[4 * i + 1], ka.y);
                        FFMA2(s2, q2[4 * i + 2], kb.x);
                        FFMA2(s3, q2[4 * i + 3], kb.y);
                    }
                    FADD2(s0, s0, s1);
                    FADD2(s2, s2, s3);
                    FADD2(s0, s0, s2);
                    unsigned slo, shi;
                    UNPACK2(slo, shi, s0);
                    float sdot = __uint_as_float(slo) + __uint_as_float(shi);
                    float p = __expf(fmaf(sdot, 0.17677669529663689f, gbv[jj]));
                    Ps[c * PSTRIDE + gene] = to_tf32(p);
                }
                gb = gbn;
            }
        }
        __syncthreads();

        // ---- phase B: D += P @ V_ext^T via mma.sync tf32 ----
        #pragma unroll 2
        for (int k8 = 0; k8 < CT / 8; ++k8) {
            int k0 = k8 * 8;
            const float* pA = Ps + (k0 + acol) * PSTRIDE + arow;
            uint32_t a0 = __float_as_uint(pA[0]);
            uint32_t a1 = __float_as_uint(pA[8]);
            uint32_t a2 = __float_as_uint(pA[4 * PSTRIDE]);
            uint32_t a3 = __float_as_uint(pA[4 * PSTRIDE + 8]);
            const float* pB = Vs + (k0 + bk) * VSTRIDE + bn;
            #pragma unroll
            for (int nt = 0; nt < NT; ++nt) {
                uint32_t b0 = __float_as_uint(pB[nt * 8]);
                uint32_t b1 = __float_as_uint(pB[4 * VSTRIDE + nt * 8]);
                mma_tf32(acc[nt], a0, a1, a2, a3, b0, b1);
            }
        }
    }

    // ---- epilogue: scatter D fragments to split partials ----
    {
        float* pbase = g_pnum + (size_t)split * (ZD * NG);
        float* dbase = g_pden + split * NG;
        int gl = blockIdx.x * GT + arow;
        int gh = gl + 8;
        #pragma unroll
        for (int nt = 0; nt < NT; ++nt) {
            int z0 = nt * 8 + 2 * (lane & 3);
            #pragma unroll
            for (int zz = 0; zz < 2; ++zz) {
                int z = z0 + zz;
                if (z < ZD) {
                    if (gl < NG) pbase[(size_t)z * NG + gl] = acc[nt][zz];
                    if (gh < NG) pbase[(size_t)z * NG + gh] = acc[nt][2 + zz];
                } else if (z == ZD) {
                    if (gl < NG) dbase[gl] = acc[nt][zz];
                    if (gh < NG) dbase[gh] = acc[nt][2 + zz];
                }
            }
        }
    }
}

// ---------------- reduce: sum splits, divide, emit (z, gene) ----------------
__global__ void reduce_kernel(float* __restrict__ out) {
    int i4 = blockIdx.x * blockDim.x + threadIdx.x;
    int base = i4 * 4;
    if (base >= ZD * NG) return;
    int gidx = base % NG;
    float4 num = make_float4(0.f, 0.f, 0.f, 0.f);
    float4 den = make_float4(0.f, 0.f, 0.f, 0.f);
    #pragma unroll
    for (int s = 0; s < NSPLIT; ++s) {
        float4 n = *reinterpret_cast<const float4*>(g_pnum + (size_t)s * (ZD * NG) + base);
        float4 d = *reinterpret_cast<const float4*>(g_pden + s * NG + gidx);
        num.x += n.x; num.y += n.y; num.z += n.z; num.w += n.w;
        den.x += d.x; den.y += d.y; den.z += d.z; den.w += d.w;
    }
    float4 o;
    o.x = num.x / den.x; o.y = num.y / den.y; o.z = num.z / den.z; o.w = num.w / den.w;
    *reinterpret_cast<float4*>(out + base) = o;
}

// ---------------- launch ----------------
extern "C" void kernel_launch(void* const* d_in, const int* in_sizes, int n_in,
                              void* d_out, int out_size) {
    const float* rawZ   = (const float*)d_in[0];
    const float* genZ   = (const float*)d_in[1];
    const float* Grep   = (const float*)d_in[2];
    const float* gumbel = (const float*)d_in[3];
    const float* Wz1 = (const float*)d_in[4];
    const float* bz1 = (const float*)d_in[5];
    const float* Wz2 = (const float*)d_in[6];
    const float* bz2 = (const float*)d_in[7];
    const float* Wg1 = (const float*)d_in[8];
    const float* bg1 = (const float*)d_in[9];
    const float* Wg2 = (const float*)d_in[10];
    const float* bg2 = (const float*)d_in[11];
    float* out = (float*)d_out;

    cudaFuncSetAttribute(decoder_main_kernel,
                         cudaFuncAttributeMaxDynamicSharedMemorySize, SMEM_MAIN);

    key_mlp_kernel<<<NC / 32, 256>>>(rawZ, Wz1, bz1, Wz2, bz2);
    query_mlp_kernel<<<(NG + 63) / 64, 64>>>(Grep, Wg1, bg1, Wg2, bg2);

    dim3 grid((NG + GT - 1) / GT, NSPLIT);
    decoder_main_kernel<<<grid, THREADS, SMEM_MAIN>>>(gumbel, genZ);

    reduce_kernel<<<(ZD * NG / 4 + 255) / 256, 256>>>(out);
}

// round 6
// speedup vs baseline: 1.6192x; 1.3172x over previous
#include <cuda_runtime.h>
#include <math.h>
#include <stdint.h>

#define NG 10000      // genes
#define NC 8192       // cells
#define ZD 100        // z dim
#define KD 32         // key dim
#define HD 256        // hidden dim (key MLP)
#define GT 128        // genes per CTA (= M)
#define CT 128        // cells per chunk (= K of PV mma)
#define NSPLIT 16     // cell splits
#define CPC (NC / NSPLIT)        // 512 cells per CTA
#define NCHUNK (CPC / CT)        // 4 chunks
#define NEXT 104      // N of PV mma (100 z + ones row + pad)
#define NT 13         // n8 tiles total
#define THREADS 512
#define PSTRIDE 136   // Ps row stride (floats)
#define VSTRIDE 105   // Vs row stride (floats)
#define GSTRIDE 132   // Gs row stride (floats): float4-aligned, LDS/STS.128 conflict-free

typedef unsigned long long u64;

// ---------------- packed f32x2 helpers ----------------
#define FFMA2(d, a, b) asm("fma.rn.f32x2 %0, %1, %2, %0;" : "+l"(d) : "l"(a), "l"(b))
#define FADD2(d, a, b) asm("add.rn.f32x2 %0, %1, %2;" : "=l"(d) : "l"(a), "l"(b))
#define UNPACK2(lo, hi, in) asm("mov.b64 {%0, %1}, %2;" : "=r"(lo), "=r"(hi) : "l"(in))

__device__ __forceinline__ float to_tf32(float x) {
    uint32_t r;
    asm("cvt.rna.tf32.f32 %0, %1;" : "=r"(r) : "f"(x));
    return __uint_as_float(r);
}

// m16n8k8 tf32 mma, C=D accum
__device__ __forceinline__ void mma_tf32(float* c,
                                         uint32_t a0, uint32_t a1, uint32_t a2, uint32_t a3,
                                         uint32_t b0, uint32_t b1) {
    asm volatile(
        "mma.sync.aligned.m16n8k8.row.col.f32.tf32.tf32.f32 "
        "{%0,%1,%2,%3}, {%4,%5,%6,%7}, {%8,%9}, {%0,%1,%2,%3};"
        : "+f"(c[0]), "+f"(c[1]), "+f"(c[2]), "+f"(c[3])
        : "r"(a0), "r"(a1), "r"(a2), "r"(a3), "r"(b0), "r"(b1));
}

__device__ __forceinline__ float gelu_exact(float x) {
    return 0.5f * x * (1.0f + erff(x * 0.70710678118654752440f));
}

// ---------------- device scratch ----------------
__device__ __align__(16) float g_key[NC * KD];           // [cell][k]
__device__ __align__(16) float g_query[NG * KD];         // [gene][k]
__device__ __align__(16) float g_pnum[NSPLIT * ZD * NG]; // [split][z][gene]
__device__ __align__(16) float g_pden[NSPLIT * NG];      // [split][gene]

// ---------------- kernel A: key MLP (cells) ----------------
__global__ void __launch_bounds__(256, 1)
key_mlp_kernel(const float* __restrict__ rawZ,
               const float* __restrict__ Wz1, const float* __restrict__ bz1,
               const float* __restrict__ Wz2, const float* __restrict__ bz2) {
    __shared__ float Zs[ZD * 32];
    __shared__ float Hs[32 * HD];
    int tid = threadIdx.x;
    int c0 = blockIdx.x * 32;

    for (int idx = tid; idx < ZD * 32; idx += 256) {
        int k = idx >> 5, cc = idx & 31;
        Zs[idx] = rawZ[(size_t)k * NC + c0 + cc];
    }
    __syncthreads();
    {
        int h = tid;
        float w[ZD];
        #pragma unroll
        for (int k = 0; k < ZD; ++k) w[k] = Wz1[k * HD + h];
        float b = bz1[h];
        for (int cc = 0; cc < 32; ++cc) {
            float a = b;
            #pragma unroll
            for (int k = 0; k < ZD; ++k) a = fmaf(Zs[k * 32 + cc], w[k], a);
            Hs[cc * HD + h] = gelu_exact(a);
        }
    }
    __syncthreads();
    for (int idx = tid; idx < 32 * KD; idx += 256) {
        int cc = idx >> 5, kk = idx & 31;
        float a = bz2[kk];
        #pragma unroll 8
        for (int h = 0; h < HD; ++h) a = fmaf(Hs[cc * HD + h], Wz2[h * KD + kk], a);
        g_key[(size_t)(c0 + cc) * KD + kk] = a;
    }
}

// ---------------- kernel B: query MLP (genes) ----------------
__global__ void query_mlp_kernel(const float* __restrict__ Grep,
                                 const float* __restrict__ Wg1, const float* __restrict__ bg1,
                                 const float* __restrict__ Wg2, const float* __restrict__ bg2) {
    __shared__ float Gs[64 * 101];
    __shared__ float W1s[100 * 32];
    __shared__ float W2s[32 * 32];
    __shared__ float b1s[32], b2s[32];
    int tid = threadIdx.x;
    int g0 = blockIdx.x * 64;
    int valid = min(64, NG - g0);

    for (int idx = tid; idx < valid * 100; idx += 64) {
        int r = idx / 100, c = idx - r * 100;
        Gs[r * 101 + c] = Grep[(size_t)g0 * 100 + idx];
    }
    for (int idx = tid; idx < 100 * 32; idx += 64) W1s[idx] = Wg1[idx];
    for (int idx = tid; idx < 32 * 32; idx += 64) W2s[idx] = Wg2[idx];
    if (tid < 32) { b1s[tid] = bg1[tid]; b2s[tid] = bg2[tid]; }
    __syncthreads();

    if (tid < valid) {
        float hid[32];
        #pragma unroll
        for (int j = 0; j < 32; ++j) hid[j] = b1s[j];
        for (int k = 0; k < 100; ++k) {
            float gv = Gs[tid * 101 + k];
            #pragma unroll
            for (int j = 0; j < 32; ++j) hid[j] = fmaf(gv, W1s[k * 32 + j], hid[j]);
        }
        #pragma unroll
        for (int j = 0; j < 32; ++j) hid[j] = gelu_exact(hid[j]);
        int g = g0 + tid;
        #pragma unroll 4
        for (int kk = 0; kk < 32; ++kk) {
            float a = b2s[kk];
            #pragma unroll
            for (int j = 0; j < 32; ++j) a = fmaf(hid[j], W2s[j * 32 + kk], a);
            g_query[(size_t)g * KD + kk] = a;
        }
    }
}

// ---------------- main fused kernel ----------------
// smem (floats): Ps[CT][PSTRIDE], Vs[CT][VSTRIDE], Ks[CT][KD], Gs[GT][GSTRIDE]
#define PS_OFF 0
#define VS_OFF (CT * PSTRIDE)                    // 17408
#define KS_OFF (VS_OFF + CT * VSTRIDE)           // 30848
#define GS_OFF (KS_OFF + CT * KD)                // 34944
#define SMEM_FLOATS (GS_OFF + GT * GSTRIDE)      // 51840
#define SMEM_MAIN (SMEM_FLOATS * 4)              // 207360 B

__global__ void __launch_bounds__(THREADS, 1)
decoder_main_kernel(const float* __restrict__ gumbel,
                    const float* __restrict__ genZ) {
    extern __shared__ float smem[];
    float* Ps = smem + PS_OFF;
    float* Vs = smem + VS_OFF;
    float* Ks = smem + KS_OFF;
    float* Gs = smem + GS_OFF;

    int tid = threadIdx.x;
    int wid = tid >> 5;
    int lane = tid & 31;
    int split = blockIdx.y;

    // phase-A identity: 4 threads per gene, each owns a 32-cell quarter
    int gene = tid & (GT - 1);
    int quarter = tid >> 7;
    int g = blockIdx.x * GT + gene;
    int gload = min(g, NG - 1);

    // phase-B identity: warp -> (m-tile, n-group)
    int mw = wid & 7;               // m16 tile
    int ng = wid >> 3;              // n-group: 0 -> nt 0..6, 1 -> nt 7..12
    int ntbase = ng * 7;
    int ntcnt = ng ? 6 : 7;
    int arow = mw * 16 + (lane >> 2);
    int acol = lane & 3;
    int bn = lane >> 2;
    int bk = lane & 3;

    // query row in packed regs (exact fp32)
    u64 q2[KD / 2];
    {
        const ulonglong2* qp = reinterpret_cast<const ulonglong2*>(g_query + (size_t)gload * KD);
        #pragma unroll
        for (int i = 0; i < KD / 4; ++i) {
            ulonglong2 t = qp[i];
            q2[2 * i] = t.x; q2[2 * i + 1] = t.y;
        }
    }

    float acc[7][4];
    #pragma unroll
    for (int i = 0; i < 7; ++i) {
        acc[i][0] = 0.f; acc[i][1] = 0.f; acc[i][2] = 0.f; acc[i][3] = 0.f;
    }

    for (int t = 0; t < NCHUNK; ++t) {
        int cbase = split * CPC + t * CT;
        __syncthreads();   // protect smem reuse from previous phase B

        // ---- stage V_ext (tf32, [cell][z] stride 105) ----
        for (int idx = tid; idx < NEXT * CT; idx += THREADS) {
            int z = idx >> 7, c = idx & (CT - 1);
            float v;
            if (z < ZD)       v = genZ[(size_t)z * NC + cbase + c];
            else if (z == ZD) v = 1.0f;     // ones row -> denominator
            else              v = 0.0f;
            Vs[c * VSTRIDE + z] = to_tf32(v);
        }
        // ---- stage K tile (contiguous) ----
        {
            const float4* src = reinterpret_cast<const float4*>(g_key + (size_t)cbase * KD);
            float4* dst = reinterpret_cast<float4*>(Ks);
            #pragma unroll
            for (int i = 0; i < (CT * KD / 4) / THREADS; ++i)
                dst[tid + i * THREADS] = src[tid + i * THREADS];
        }
        // ---- stage gumbel tile coalesced: Gs[gene][cell], stride 132 ----
        {
            #pragma unroll
            for (int i = 0; i < (GT * 32) / THREADS; ++i) {
                int idx = tid + i * THREADS;
                int gr = idx >> 5, c4 = idx & 31;
                int grow = min(blockIdx.x * GT + gr, NG - 1);
                float4 v = *reinterpret_cast<const float4*>(
                    gumbel + (size_t)grow * NC + cbase + c4 * 4);
                *reinterpret_cast<float4*>(Gs + gr * GSTRIDE + c4 * 4) = v;
            }
        }
        __syncthreads();

        // ---- phase A: p for this thread's 32 cells -> Ps (tf32 bits) ----
        {
            int cq = quarter * 32;
            #pragma unroll 1
            for (int c0 = cq; c0 < cq + 32; c0 += 4) {
                float4 gb = *reinterpret_cast<const float4*>(Gs + gene * GSTRIDE + c0);
                float gbv[4] = {gb.x, gb.y, gb.z, gb.w};
                #pragma unroll
                for (int jj = 0; jj < 4; ++jj) {
                    int c = c0 + jj;
                    const ulonglong2* kp = reinterpret_cast<const ulonglong2*>(Ks + c * KD);
                    u64 s0 = 0ULL, s1 = 0ULL, s2 = 0ULL, s3 = 0ULL;
                    #pragma unroll
                    for (int i = 0; i < 4; ++i) {
                        ulonglong2 ka = kp[2 * i];
                        ulonglong2 kb = kp[2 * i + 1];
                        FFMA2(s0, q2[4 * i + 0], ka.x);
                        FFMA2(s1, q2[4 * i + 1], ka.y);
                        FFMA2(s2, q2[4 * i + 2], kb.x);
                        FFMA2(s3, q2[4 * i + 3], kb.y);
                    }
                    FADD2(s0, s0, s1);
                    FADD2(s2, s2, s3);
                    FADD2(s0, s0, s2);
                    unsigned slo, shi;
                    UNPACK2(slo, shi, s0);
                    float sdot = __uint_as_float(slo) + __uint_as_float(shi);
                    float p = __expf(fmaf(sdot, 0.17677669529663689f, gbv[jj]));
                    Ps[c * PSTRIDE + gene] = to_tf32(p);
                }
            }
        }
        __syncthreads();

        // ---- phase B: D += P @ V_ext^T via mma.sync tf32 (split n-tiles) ----
        #pragma unroll 2
        for (int k8 = 0; k8 < CT / 8; ++k8) {
            int k0 = k8 * 8;
            const float* pA = Ps + (k0 + acol) * PSTRIDE + arow;
            uint32_t a0 = __float_as_uint(pA[0]);
            uint32_t a1 = __float_as_uint(pA[8]);
            uint32_t a2 = __float_as_uint(pA[4 * PSTRIDE]);
            uint32_t a3 = __float_as_uint(pA[4 * PSTRIDE + 8]);
            const float* pB = Vs + (k0 + bk) * VSTRIDE + bn + ntbase * 8;
            #pragma unroll
            for (int i = 0; i < 7; ++i) {
                if (i < ntcnt) {
                    uint32_t b0 = __float_as_uint(pB[i * 8]);
                    uint32_t b1 = __float_as_uint(pB[4 * VSTRIDE + i * 8]);
                    mma_tf32(acc[i], a0, a1, a2, a3, b0, b1);
                }
            }
        }
    }

    // ---- epilogue: scatter D fragments to split partials ----
    {
        float* pbase = g_pnum + (size_t)split * (ZD * NG);
        float* dbase = g_pden + split * NG;
        int gl = blockIdx.x * GT + arow;
        int gh = gl + 8;
        #pragma unroll
        for (int i = 0; i < 7; ++i) {
            if (i < ntcnt) {
                int nt = ntbase + i;
                int z0 = nt * 8 + 2 * (lane & 3);
                #pragma unroll
                for (int zz = 0; zz < 2; ++zz) {
                    int z = z0 + zz;
                    if (z < ZD) {
                        if (gl < NG) pbase[(size_t)z * NG + gl] = acc[i][zz];
                        if (gh < NG) pbase[(size_t)z * NG + gh] = acc[i][2 + zz];
                    } else if (z == ZD) {
                        if (gl < NG) dbase[gl] = acc[i][zz];
                        if (gh < NG) dbase[gh] = acc[i][2 + zz];
                    }
                }
            }
        }
    }
}

// ---------------- reduce: sum splits, divide, emit (z, gene) ----------------
__global__ void reduce_kernel(float* __restrict__ out) {
    int i4 = blockIdx.x * blockDim.x + threadIdx.x;
    int base = i4 * 4;
    if (base >= ZD * NG) return;
    int gidx = base % NG;
    float4 num = make_float4(0.f, 0.f, 0.f, 0.f);
    float4 den = make_float4(0.f, 0.f, 0.f, 0.f);
    #pragma unroll
    for (int s = 0; s < NSPLIT; ++s) {
        float4 n = *reinterpret_cast<const float4*>(g_pnum + (size_t)s * (ZD * NG) + base);
        float4 d = *reinterpret_cast<const float4*>(g_pden + s * NG + gidx);
        num.x += n.x; num.y += n.y; num.z += n.z; num.w += n.w;
        den.x += d.x; den.y += d.y; den.z += d.z; den.w += d.w;
    }
    float4 o;
    o.x = num.x / den.x; o.y = num.y / den.y; o.z = num.z / den.z; o.w = num.w / den.w;
    *reinterpret_cast<float4*>(out + base) = o;
}

// ---------------- launch ----------------
extern "C" void kernel_launch(void* const* d_in, const int* in_sizes, int n_in,
                              void* d_out, int out_size) {
    const float* rawZ   = (const float*)d_in[0];
    const float* genZ   = (const float*)d_in[1];
    const float* Grep   = (const float*)d_in[2];
    const float* gumbel = (const float*)d_in[3];
    const float* Wz1 = (const float*)d_in[4];
    const float* bz1 = (const float*)d_in[5];
    const float* Wz2 = (const float*)d_in[6];
    const float* bz2 = (const float*)d_in[7];
    const float* Wg1 = (const float*)d_in[8];
    const float* bg1 = (const float*)d_in[9];
    const float* Wg2 = (const float*)d_in[10];
    const float* bg2 = (const float*)d_in[11];
    float* out = (float*)d_out;

    cudaFuncSetAttribute(decoder_main_kernel,
                         cudaFuncAttributeMaxDynamicSharedMemorySize, SMEM_MAIN);

    key_mlp_kernel<<<NC / 32, 256>>>(rawZ, Wz1, bz1, Wz2, bz2);
    query_mlp_kernel<<<(NG + 63) / 64, 64>>>(Grep, Wg1, bg1, Wg2, bg2);

    dim3 grid((NG + GT - 1) / GT, NSPLIT);
    decoder_main_kernel<<<grid, THREADS, SMEM_MAIN>>>(gumbel, genZ);

    reduce_kernel<<<(ZD * NG / 4 + 255) / 256, 256>>>(out);
}

// round 7
// speedup vs baseline: 2.0513x; 1.2669x over previous
#include <cuda_runtime.h>
#include <math.h>
#include <stdint.h>

#define NG 10000      // genes
#define NC 8192       // cells
#define ZD 100        // z dim
#define KD 32         // key dim
#define HD 256        // hidden dim (key MLP)
#define GT 128        // genes per CTA (= M)
#define CT 128        // cells per chunk
#define NSPLIT 16     // cell splits
#define CPC (NC / NSPLIT)        // 512 cells per CTA
#define NCHUNK (CPC / CT)        // 4 chunks
#define NEXT 104      // N of PV mma (100 z + ones row + pad)
#define THREADS 512

#define QSTR 36       // Qs/Ks row stride: 4*r+c banks all distinct
#define KSTR 36
#define VSTRIDE 105
#define GSTRIDE 132
#define PSTRIDE 136

// log2(e), log2(e)/sqrt(32)
#define L2E 1.4426950408889634f
#define SCALE_S 0.25503482f

typedef unsigned long long u64;

__device__ __forceinline__ float to_tf32(float x) {
    uint32_t r;
    asm("cvt.rna.tf32.f32 %0, %1;" : "=r"(r) : "f"(x));
    return __uint_as_float(r);
}

// m16n8k8 tf32 mma, C=D accum
__device__ __forceinline__ void mma_tf32(float* c,
                                         uint32_t a0, uint32_t a1, uint32_t a2, uint32_t a3,
                                         uint32_t b0, uint32_t b1) {
    asm volatile(
        "mma.sync.aligned.m16n8k8.row.col.f32.tf32.tf32.f32 "
        "{%0,%1,%2,%3}, {%4,%5,%6,%7}, {%8,%9}, {%0,%1,%2,%3};"
        : "+f"(c[0]), "+f"(c[1]), "+f"(c[2]), "+f"(c[3])
        : "r"(a0), "r"(a1), "r"(a2), "r"(a3), "r"(b0), "r"(b1));
}

__device__ __forceinline__ float gelu_exact(float x) {
    return 0.5f * x * (1.0f + erff(x * 0.70710678118654752440f));
}

// ---------------- device scratch ----------------
__device__ __align__(16) float g_key[NC * KD];           // [cell][k]
__device__ __align__(16) float g_query[NG * KD];         // [gene][k]
__device__ __align__(16) float g_pnum[NSPLIT * ZD * NG]; // [split][z][gene]
__device__ __align__(16) float g_pden[NSPLIT * NG];      // [split][gene]

// ---------------- kernel A: key MLP (cells) ----------------
__global__ void __launch_bounds__(256, 1)
key_mlp_kernel(const float* __restrict__ rawZ,
               const float* __restrict__ Wz1, const float* __restrict__ bz1,
               const float* __restrict__ Wz2, const float* __restrict__ bz2) {
    __shared__ float Zs[ZD * 32];
    __shared__ float Hs[32 * HD];
    int tid = threadIdx.x;
    int c0 = blockIdx.x * 32;

    for (int idx = tid; idx < ZD * 32; idx += 256) {
        int k = idx >> 5, cc = idx & 31;
        Zs[idx] = rawZ[(size_t)k * NC + c0 + cc];
    }
    __syncthreads();
    {
        int h = tid;
        float w[ZD];
        #pragma unroll
        for (int k = 0; k < ZD; ++k) w[k] = Wz1[k * HD + h];
        float b = bz1[h];
        for (int cc = 0; cc < 32; ++cc) {
            float a = b;
            #pragma unroll
            for (int k = 0; k < ZD; ++k) a = fmaf(Zs[k * 32 + cc], w[k], a);
            Hs[cc * HD + h] = gelu_exact(a);
        }
    }
    __syncthreads();
    for (int idx = tid; idx < 32 * KD; idx += 256) {
        int cc = idx >> 5, kk = idx & 31;
        float a = bz2[kk];
        #pragma unroll 8
        for (int h = 0; h < HD; ++h) a = fmaf(Hs[cc * HD + h], Wz2[h * KD + kk], a);
        g_key[(size_t)(c0 + cc) * KD + kk] = a;
    }
}

// ---------------- kernel B: query MLP (genes) ----------------
__global__ void query_mlp_kernel(const float* __restrict__ Grep,
                                 const float* __restrict__ Wg1, const float* __restrict__ bg1,
                                 const float* __restrict__ Wg2, const float* __restrict__ bg2) {
    __shared__ float Gs[64 * 101];
    __shared__ float W1s[100 * 32];
    __shared__ float W2s[32 * 32];
    __shared__ float b1s[32], b2s[32];
    int tid = threadIdx.x;
    int g0 = blockIdx.x * 64;
    int valid = min(64, NG - g0);

    for (int idx = tid; idx < valid * 100; idx += 64) {
        int r = idx / 100, c = idx - r * 100;
        Gs[r * 101 + c] = Grep[(size_t)g0 * 100 + idx];
    }
    for (int idx = tid; idx < 100 * 32; idx += 64) W1s[idx] = Wg1[idx];
    for (int idx = tid; idx < 32 * 32; idx += 64) W2s[idx] = Wg2[idx];
    if (tid < 32) { b1s[tid] = bg1[tid]; b2s[tid] = bg2[tid]; }
    __syncthreads();

    if (tid < valid) {
        float hid[32];
        #pragma unroll
        for (int j = 0; j < 32; ++j) hid[j] = b1s[j];
        for (int k = 0; k < 100; ++k) {
            float gv = Gs[tid * 101 + k];
            #pragma unroll
            for (int j = 0; j < 32; ++j) hid[j] = fmaf(gv, W1s[k * 32 + j], hid[j]);
        }
        #pragma unroll
        for (int j = 0; j < 32; ++j) hid[j] = gelu_exact(hid[j]);
        int g = g0 + tid;
        #pragma unroll 4
        for (int kk = 0; kk < 32; ++kk) {
            float a = b2s[kk];
            #pragma unroll
            for (int j = 0; j < 32; ++j) a = fmaf(hid[j], W2s[j * 32 + kk], a);
            g_query[(size_t)g * KD + kk] = a;
        }
    }
}

// ---------------- main fused kernel ----------------
// smem (floats)
#define QS_OFF 0
#define KS_OFF (GT * QSTR)                       // 4608
#define VS_OFF (KS_OFF + CT * KSTR)              // 9216
#define GS_OFF (VS_OFF + CT * VSTRIDE)           // 22656
#define PS_OFF (GS_OFF + GT * GSTRIDE)           // 39552
#define SMEM_FLOATS (PS_OFF + CT * PSTRIDE)      // 56960
#define SMEM_MAIN (SMEM_FLOATS * 4)              // 227840 B

__global__ void __launch_bounds__(THREADS, 1)
decoder_main_kernel(const float* __restrict__ gumbel,
                    const float* __restrict__ genZ) {
    extern __shared__ float smem[];
    float* Qs = smem + QS_OFF;
    float* Ks = smem + KS_OFF;
    float* Vs = smem + VS_OFF;
    float* Gs = smem + GS_OFF;
    float* Ps = smem + PS_OFF;

    int tid = threadIdx.x;
    int wid = tid >> 5;
    int lane = tid & 31;
    int split = blockIdx.y;

    int mw = wid & 7;               // m16 tile
    int ng = wid >> 3;              // n-group (cells halves for S; n-tiles 0..6/7..12 for PV)
    int lr = lane >> 2;             // fragment row group / B n-offset
    int lc = lane & 3;              // fragment col group / B k-offset
    int arow = mw * 16 + lr;

    // PV n-tile split
    int ntbase = ng * 7;
    int ntcnt = ng ? 6 : 7;

    // ---- stage Q (tf32) once per CTA ----
    {
        #pragma unroll
        for (int i = 0; i < (GT * KD) / THREADS; ++i) {
            int idx = tid + i * THREADS;
            int gr = idx >> 5, k = idx & 31;
            int grow = min(blockIdx.x * GT + gr, NG - 1);
            Qs[gr * QSTR + k] = to_tf32(g_query[(size_t)grow * KD + k]);
        }
    }

    float acc[7][4];
    #pragma unroll
    for (int i = 0; i < 7; ++i) {
        acc[i][0] = 0.f; acc[i][1] = 0.f; acc[i][2] = 0.f; acc[i][3] = 0.f;
    }

    for (int t = 0; t < NCHUNK; ++t) {
        int cbase = split * CPC + t * CT;
        __syncthreads();   // protect smem reuse from previous chunk's readers

        // ---- stage K tile (tf32, [cell][k] stride 36) ----
        {
            #pragma unroll
            for (int i = 0; i < (CT * KD) / THREADS; ++i) {
                int idx = tid + i * THREADS;
                int c = idx >> 5, k = idx & 31;
                Ks[c * KSTR + k] = to_tf32(g_key[(size_t)(cbase + c) * KD + k]);
            }
        }
        // ---- stage V_ext (tf32, [cell][z] stride 105) ----
        for (int idx = tid; idx < NEXT * CT; idx += THREADS) {
            int z = idx >> 7, c = idx & (CT - 1);
            float v;
            if (z < ZD)       v = genZ[(size_t)z * NC + cbase + c];
            else if (z == ZD) v = 1.0f;     // ones row -> denominator
            else              v = 0.0f;
            Vs[c * VSTRIDE + z] = to_tf32(v);
        }
        // ---- stage gumbel tile coalesced, prescaled by log2(e) ----
        {
            #pragma unroll
            for (int i = 0; i < (GT * 32) / THREADS; ++i) {
                int idx = tid + i * THREADS;
                int gr = idx >> 5, c4 = idx & 31;
                int grow = min(blockIdx.x * GT + gr, NG - 1);
                float4 v = *reinterpret_cast<const float4*>(
                    gumbel + (size_t)grow * NC + cbase + c4 * 4);
                v.x *= L2E; v.y *= L2E; v.z *= L2E; v.w *= L2E;
                *reinterpret_cast<float4*>(Gs + gr * GSTRIDE + c4 * 4) = v;
            }
        }
        __syncthreads();

        // ---- phase S: S = Q@K^T via mma.sync; each warp m16 x 8 n8-tiles ----
        {
            float sacc[8][4];
            #pragma unroll
            for (int i = 0; i < 8; ++i) {
                sacc[i][0] = 0.f; sacc[i][1] = 0.f; sacc[i][2] = 0.f; sacc[i][3] = 0.f;
            }
            #pragma unroll
            for (int k8 = 0; k8 < 4; ++k8) {
                int k0 = k8 * 8;
                const float* qA = Qs + arow * QSTR + k0 + lc;
                uint32_t a0 = __float_as_uint(qA[0]);
                uint32_t a1 = __float_as_uint(qA[8 * QSTR]);
                uint32_t a2 = __float_as_uint(qA[4]);
                uint32_t a3 = __float_as_uint(qA[8 * QSTR + 4]);
                const float* kB = Ks + (ng * 64 + lr) * KSTR + k0 + lc;
                #pragma unroll
                for (int i = 0; i < 8; ++i) {
                    uint32_t b0 = __float_as_uint(kB[i * 8 * KSTR]);
                    uint32_t b1 = __float_as_uint(kB[i * 8 * KSTR + 4]);
                    mma_tf32(sacc[i], a0, a1, a2, a3, b0, b1);
                }
            }
            // exp + scatter to Ps[cell][gene] (tf32 bits)
            #pragma unroll
            for (int i = 0; i < 8; ++i) {
                int c0 = ng * 64 + i * 8 + 2 * lc;
                float g00 = Gs[arow * GSTRIDE + c0];
                float g01 = Gs[arow * GSTRIDE + c0 + 1];
                float g10 = Gs[(arow + 8) * GSTRIDE + c0];
                float g11 = Gs[(arow + 8) * GSTRIDE + c0 + 1];
                float p00 = exp2f(fmaf(sacc[i][0], SCALE_S, g00));
                float p01 = exp2f(fmaf(sacc[i][1], SCALE_S, g01));
                float p10 = exp2f(fmaf(sacc[i][2], SCALE_S, g10));
                float p11 = exp2f(fmaf(sacc[i][3], SCALE_S, g11));
                Ps[c0 * PSTRIDE + arow] = to_tf32(p00);
                Ps[(c0 + 1) * PSTRIDE + arow] = to_tf32(p01);
                Ps[c0 * PSTRIDE + arow + 8] = to_tf32(p10);
                Ps[(c0 + 1) * PSTRIDE + arow + 8] = to_tf32(p11);
            }
        }
        __syncthreads();

        // ---- phase PV: D += P @ V_ext^T via mma.sync (split n-tiles) ----
        #pragma unroll 2
        for (int k8 = 0; k8 < CT / 8; ++k8) {
            int k0 = k8 * 8;
            const float* pA = Ps + (k0 + lc) * PSTRIDE + arow;
            uint32_t a0 = __float_as_uint(pA[0]);
            uint32_t a1 = __float_as_uint(pA[8]);
            uint32_t a2 = __float_as_uint(pA[4 * PSTRIDE]);
            uint32_t a3 = __float_as_uint(pA[4 * PSTRIDE + 8]);
            const float* pB = Vs + (k0 + lc) * VSTRIDE + lr + ntbase * 8;
            #pragma unroll
            for (int i = 0; i < 7; ++i) {
                if (i < ntcnt) {
                    uint32_t b0 = __float_as_uint(pB[i * 8]);
                    uint32_t b1 = __float_as_uint(pB[4 * VSTRIDE + i * 8]);
                    mma_tf32(acc[i], a0, a1, a2, a3, b0, b1);
                }
            }
        }
    }

    // ---- epilogue: scatter D fragments to split partials ----
    {
        float* pbase = g_pnum + (size_t)split * (ZD * NG);
        float* dbase = g_pden + split * NG;
        int gl = blockIdx.x * GT + arow;
        int gh = gl + 8;
        #pragma unroll
        for (int i = 0; i < 7; ++i) {
            if (i < ntcnt) {
                int nt = ntbase + i;
                int z0 = nt * 8 + 2 * lc;
                #pragma unroll
                for (int zz = 0; zz < 2; ++zz) {
                    int z = z0 + zz;
                    if (z < ZD) {
                        if (gl < NG) pbase[(size_t)z * NG + gl] = acc[i][zz];
                        if (gh < NG) pbase[(size_t)z * NG + gh] = acc[i][2 + zz];
                    } else if (z == ZD) {
                        if (gl < NG) dbase[gl] = acc[i][zz];
                        if (gh < NG) dbase[gh] = acc[i][2 + zz];
                    }
                }
            }
        }
    }
}

// ---------------- reduce: sum splits, divide, emit (z, gene) ----------------
__global__ void reduce_kernel(float* __restrict__ out) {
    int i4 = blockIdx.x * blockDim.x + threadIdx.x;
    int base = i4 * 4;
    if (base >= ZD * NG) return;
    int gidx = base % NG;
    float4 num = make_float4(0.f, 0.f, 0.f, 0.f);
    float4 den = make_float4(0.f, 0.f, 0.f, 0.f);
    #pragma unroll
    for (int s = 0; s < NSPLIT; ++s) {
        float4 n = *reinterpret_cast<const float4*>(g_pnum + (size_t)s * (ZD * NG) + base);
        float4 d = *reinterpret_cast<const float4*>(g_pden + s * NG + gidx);
        num.x += n.x; num.y += n.y; num.z += n.z; num.w += n.w;
        den.x += d.x; den.y += d.y; den.z += d.z; den.w += d.w;
    }
    float4 o;
    o.x = num.x / den.x; o.y = num.y / den.y; o.z = num.z / den.z; o.w = num.w / den.w;
    *reinterpret_cast<float4*>(out + base) = o;
}

// ---------------- launch ----------------
extern "C" void kernel_launch(void* const* d_in, const int* in_sizes, int n_in,
                              void* d_out, int out_size) {
    const float* rawZ   = (const float*)d_in[0];
    const float* genZ   = (const float*)d_in[1];
    const float* Grep   = (const float*)d_in[2];
    const float* gumbel = (const float*)d_in[3];
    const float* Wz1 = (const float*)d_in[4];
    const float* bz1 = (const float*)d_in[5];
    const float* Wz2 = (const float*)d_in[6];
    const float* bz2 = (const float*)d_in[7];
    const float* Wg1 = (const float*)d_in[8];
    const float* bg1 = (const float*)d_in[9];
    const float* Wg2 = (const float*)d_in[10];
    const float* bg2 = (const float*)d_in[11];
    float* out = (float*)d_out;

    cudaFuncSetAttribute(decoder_main_kernel,
                         cudaFuncAttributeMaxDynamicSharedMemorySize, SMEM_MAIN);

    key_mlp_kernel<<<NC / 32, 256>>>(rawZ, Wz1, bz1, Wz2, bz2);
    query_mlp_kernel<<<(NG + 63) / 64, 64>>>(Grep, Wg1, bg1, Wg2, bg2);

    dim3 grid((NG + GT - 1) / GT, NSPLIT);
    decoder_main_kernel<<<grid, THREADS, SMEM_MAIN>>>(gumbel, genZ);

    reduce_kernel<<<(ZD * NG / 4 + 255) / 256, 256>>>(out);
}

// round 8
// speedup vs baseline: 2.5481x; 1.2422x over previous
#include <cuda_runtime.h>
#include <math.h>
#include <stdint.h>

#define NG 10000      // genes
#define NC 8192       // cells
#define ZD 100        // z dim
#define KD 32         // key dim
#define HD 256        // hidden dim (key MLP)
#define GT 256        // genes per CTA (= M)
#define CT 64         // cells per chunk
#define NSPLIT 32     // cell splits
#define CPC (NC / NSPLIT)        // 256 cells per CTA
#define NCHUNK (CPC / CT)        // 4 chunks
#define NEXT 104      // N of PV mma (100 z + ones row + pad)
#define THREADS 512

#define KSTR 36       // Ks row stride
#define VSTR 105      // Vs row stride
#define GSTR 68       // Gs row stride (CT+4)
#define PSTR 68       // Ps row stride (CT+4)

// log2(e), log2(e)/sqrt(32)
#define L2E 1.4426950408889634f
#define SCALE_S 0.25503482f

typedef unsigned long long u64;

__device__ __forceinline__ float to_tf32(float x) {
    uint32_t r;
    asm("cvt.rna.tf32.f32 %0, %1;" : "=r"(r) : "f"(x));
    return __uint_as_float(r);
}

// m16n8k8 tf32 mma, C=D accum
__device__ __forceinline__ void mma_tf32(float* c,
                                         uint32_t a0, uint32_t a1, uint32_t a2, uint32_t a3,
                                         uint32_t b0, uint32_t b1) {
    asm volatile(
        "mma.sync.aligned.m16n8k8.row.col.f32.tf32.tf32.f32 "
        "{%0,%1,%2,%3}, {%4,%5,%6,%7}, {%8,%9}, {%0,%1,%2,%3};"
        : "+f"(c[0]), "+f"(c[1]), "+f"(c[2]), "+f"(c[3])
        : "r"(a0), "r"(a1), "r"(a2), "r"(a3), "r"(b0), "r"(b1));
}

__device__ __forceinline__ float gelu_exact(float x) {
    return 0.5f * x * (1.0f + erff(x * 0.70710678118654752440f));
}

// ---------------- device scratch ----------------
__device__ __align__(16) float g_key[NC * KD];           // [cell][k]
__device__ __align__(16) float g_query[NG * KD];         // [gene][k]
__device__ __align__(16) float g_pnum[NSPLIT * ZD * NG]; // [split][z][gene]
__device__ __align__(16) float g_pden[NSPLIT * NG];      // [split][gene]

// ---------------- kernel A: key MLP (cells) ----------------
__global__ void __launch_bounds__(256, 1)
key_mlp_kernel(const float* __restrict__ rawZ,
               const float* __restrict__ Wz1, const float* __restrict__ bz1,
               const float* __restrict__ Wz2, const float* __restrict__ bz2) {
    __shared__ float Zs[ZD * 32];
    __shared__ float Hs[32 * HD];
    int tid = threadIdx.x;
    int c0 = blockIdx.x * 32;

    for (int idx = tid; idx < ZD * 32; idx += 256) {
        int k = idx >> 5, cc = idx & 31;
        Zs[idx] = rawZ[(size_t)k * NC + c0 + cc];
    }
    __syncthreads();
    {
        int h = tid;
        float w[ZD];
        #pragma unroll
        for (int k = 0; k < ZD; ++k) w[k] = Wz1[k * HD + h];
        float b = bz1[h];
        for (int cc = 0; cc < 32; ++cc) {
            float a = b;
            #pragma unroll
            for (int k = 0; k < ZD; ++k) a = fmaf(Zs[k * 32 + cc], w[k], a);
            Hs[cc * HD + h] = gelu_exact(a);
        }
    }
    __syncthreads();
    for (int idx = tid; idx < 32 * KD; idx += 256) {
        int cc = idx >> 5, kk = idx & 31;
        float a = bz2[kk];
        #pragma unroll 8
        for (int h = 0; h < HD; ++h) a = fmaf(Hs[cc * HD + h], Wz2[h * KD + kk], a);
        g_key[(size_t)(c0 + cc) * KD + kk] = a;
    }
}

// ---------------- kernel B: query MLP (genes) ----------------
__global__ void query_mlp_kernel(const float* __restrict__ Grep,
                                 const float* __restrict__ Wg1, const float* __restrict__ bg1,
                                 const float* __restrict__ Wg2, const float* __restrict__ bg2) {
    __shared__ float Gs[64 * 101];
    __shared__ float W1s[100 * 32];
    __shared__ float W2s[32 * 32];
    __shared__ float b1s[32], b2s[32];
    int tid = threadIdx.x;
    int g0 = blockIdx.x * 64;
    int valid = min(64, NG - g0);

    for (int idx = tid; idx < valid * 100; idx += 64) {
        int r = idx / 100, c = idx - r * 100;
        Gs[r * 101 + c] = Grep[(size_t)g0 * 100 + idx];
    }
    for (int idx = tid; idx < 100 * 32; idx += 64) W1s[idx] = Wg1[idx];
    for (int idx = tid; idx < 32 * 32; idx += 64) W2s[idx] = Wg2[idx];
    if (tid < 32) { b1s[tid] = bg1[tid]; b2s[tid] = bg2[tid]; }
    __syncthreads();

    if (tid < valid) {
        float hid[32];
        #pragma unroll
        for (int j = 0; j < 32; ++j) hid[j] = b1s[j];
        for (int k = 0; k < 100; ++k) {
            float gv = Gs[tid * 101 + k];
            #pragma unroll
            for (int j = 0; j < 32; ++j) hid[j] = fmaf(gv, W1s[k * 32 + j], hid[j]);
        }
        #pragma unroll
        for (int j = 0; j < 32; ++j) hid[j] = gelu_exact(hid[j]);
        int g = g0 + tid;
        #pragma unroll 4
        for (int kk = 0; kk < 32; ++kk) {
            float a = b2s[kk];
            #pragma unroll
            for (int j = 0; j < 32; ++j) a = fmaf(hid[j], W2s[j * 32 + kk], a);
            g_query[(size_t)g * KD + kk] = a;
        }
    }
}

// ---------------- main fused kernel ----------------
// smem (floats)
#define KS_OFF 0
#define VS_OFF (CT * KSTR)                       // 2304
#define GS_OFF (VS_OFF + CT * VSTR)              // 9024
#define PS_OFF (GS_OFF + GT * GSTR)              // 26432
#define SMEM_FLOATS (PS_OFF + GT * PSTR)         // 43840
#define SMEM_MAIN (SMEM_FLOATS * 4)              // 175360 B

__global__ void __launch_bounds__(THREADS, 1)
decoder_main_kernel(const float* __restrict__ gumbel,
                    const float* __restrict__ genZ) {
    extern __shared__ float smem[];
    float* Ks = smem + KS_OFF;
    float* Vs = smem + VS_OFF;
    float* Gs = smem + GS_OFF;
    float* Ps = smem + PS_OFF;

    int tid = threadIdx.x;
    int wid = tid >> 5;
    int lane = tid & 31;
    int split = blockIdx.y;
    int gbase = blockIdx.x * GT;

    int lr = lane >> 2;             // fragment row group
    int lc = lane & 3;              // fragment col group

    // S identity: warp = one m16 tile (16 warps = 16 m-tiles = 256 genes)
    int arowS = wid * 16 + lr;

    // PV identity: 8 m-groups (2 m-tiles each) x 2 n-groups
    int mg = wid & 7;
    int ngrp = wid >> 3;
    int ntbase = ngrp * 7;
    int ntcnt = ngrp ? 6 : 7;
    int arow0 = mg * 32 + lr;       // PV m-tile 0 row; m-tile 1 = +16

    // ---- Q fragments in registers, loaded once (tf32) ----
    uint32_t qf[4][4];
    {
        int gq0 = min(gbase + arowS, NG - 1);
        int gq1 = min(gbase + arowS + 8, NG - 1);
        const float* q0 = g_query + (size_t)gq0 * KD;
        const float* q1 = g_query + (size_t)gq1 * KD;
        #pragma unroll
        for (int k8 = 0; k8 < 4; ++k8) {
            int k = k8 * 8 + lc;
            qf[k8][0] = __float_as_uint(to_tf32(q0[k]));
            qf[k8][1] = __float_as_uint(to_tf32(q1[k]));
            qf[k8][2] = __float_as_uint(to_tf32(q0[k + 4]));
            qf[k8][3] = __float_as_uint(to_tf32(q1[k + 4]));
        }
    }

    float acc[2][7][4];
    #pragma unroll
    for (int m = 0; m < 2; ++m)
        #pragma unroll
        for (int i = 0; i < 7; ++i) {
            acc[m][i][0] = 0.f; acc[m][i][1] = 0.f;
            acc[m][i][2] = 0.f; acc[m][i][3] = 0.f;
        }

    for (int t = 0; t < NCHUNK; ++t) {
        int cbase = split * CPC + t * CT;
        __syncthreads();   // protect smem reuse from previous chunk's readers

        // ---- stage K tile (tf32, [cell][k] stride 36) ----
        #pragma unroll
        for (int i = 0; i < (CT * KD) / THREADS; ++i) {
            int idx = tid + i * THREADS;
            int c = idx >> 5, k = idx & 31;
            Ks[c * KSTR + k] = to_tf32(g_key[(size_t)(cbase + c) * KD + k]);
        }
        // ---- stage V_ext (tf32, [cell][z] stride 105) ----
        #pragma unroll
        for (int i = 0; i < 13; ++i) {
            int idx = tid + i * THREADS;
            int z = idx / CT, c = idx & (CT - 1);
            float v;
            if (z < ZD)       v = genZ[(size_t)z * NC + cbase + c];
            else if (z == ZD) v = 1.0f;     // ones row -> denominator
            else              v = 0.0f;
            Vs[c * VSTR + z] = to_tf32(v);
        }
        // ---- stage gumbel tile coalesced, prescaled by log2(e) ----
        #pragma unroll
        for (int i = 0; i < (GT * (CT / 4)) / THREADS; ++i) {
            int idx = tid + i * THREADS;
            int gr = idx >> 4, c4 = idx & 15;
            int grow = min(gbase + gr, NG - 1);
            float4 v = *reinterpret_cast<const float4*>(
                gumbel + (size_t)grow * NC + cbase + c4 * 4);
            v.x *= L2E; v.y *= L2E; v.z *= L2E; v.w *= L2E;
            *reinterpret_cast<float4*>(Gs + gr * GSTR + c4 * 4) = v;
        }
        __syncthreads();

        // ---- phase S: one n8 tile at a time; exp + scatter immediately ----
        #pragma unroll
        for (int nt = 0; nt < CT / 8; ++nt) {
            float sacc[4] = {0.f, 0.f, 0.f, 0.f};
            #pragma unroll
            for (int k8 = 0; k8 < 4; ++k8) {
                const float* kB = Ks + (nt * 8 + lr) * KSTR + k8 * 8 + lc;
                uint32_t b0 = __float_as_uint(kB[0]);
                uint32_t b1 = __float_as_uint(kB[4]);
                mma_tf32(sacc, qf[k8][0], qf[k8][1], qf[k8][2], qf[k8][3], b0, b1);
            }
            int c0 = nt * 8 + 2 * lc;
            float g00 = Gs[arowS * GSTR + c0];
            float g01 = Gs[arowS * GSTR + c0 + 1];
            float g10 = Gs[(arowS + 8) * GSTR + c0];
            float g11 = Gs[(arowS + 8) * GSTR + c0 + 1];
            Ps[arowS * PSTR + c0]           = to_tf32(exp2f(fmaf(sacc[0], SCALE_S, g00)));
            Ps[arowS * PSTR + c0 + 1]       = to_tf32(exp2f(fmaf(sacc[1], SCALE_S, g01)));
            Ps[(arowS + 8) * PSTR + c0]     = to_tf32(exp2f(fmaf(sacc[2], SCALE_S, g10)));
            Ps[(arowS + 8) * PSTR + c0 + 1] = to_tf32(exp2f(fmaf(sacc[3], SCALE_S, g11)));
        }
        __syncthreads();

        // ---- phase PV: D += P @ V_ext^T ; 2 m-tiles x up-to-7 n-tiles ----
        #pragma unroll
        for (int k8 = 0; k8 < CT / 8; ++k8) {
            int k0 = k8 * 8;
            const float* pA = Ps + arow0 * PSTR + k0 + lc;
            uint32_t a00 = __float_as_uint(pA[0]);
            uint32_t a01 = __float_as_uint(pA[8 * PSTR]);
            uint32_t a02 = __float_as_uint(pA[4]);
            uint32_t a03 = __float_as_uint(pA[8 * PSTR + 4]);
            uint32_t a10 = __float_as_uint(pA[16 * PSTR]);
            uint32_t a11 = __float_as_uint(pA[24 * PSTR]);
            uint32_t a12 = __float_as_uint(pA[16 * PSTR + 4]);
            uint32_t a13 = __float_as_uint(pA[24 * PSTR + 4]);
            const float* pB = Vs + (k0 + lc) * VSTR + ntbase * 8 + lr;
            #pragma unroll
            for (int i = 0; i < 7; ++i) {
                if (i < ntcnt) {
                    uint32_t b0 = __float_as_uint(pB[i * 8]);
                    uint32_t b1 = __float_as_uint(pB[4 * VSTR + i * 8]);
                    mma_tf32(acc[0][i], a00, a01, a02, a03, b0, b1);
                    mma_tf32(acc[1][i], a10, a11, a12, a13, b0, b1);
                }
            }
        }
    }

    // ---- epilogue: scatter D fragments to split partials ----
    {
        float* pbase = g_pnum + (size_t)split * (ZD * NG);
        float* dbase = g_pden + split * NG;
        #pragma unroll
        for (int m = 0; m < 2; ++m) {
            int gl = gbase + arow0 + m * 16;
            int gh = gl + 8;
            #pragma unroll
            for (int i = 0; i < 7; ++i) {
                if (i < ntcnt) {
                    int nt = ntbase + i;
                    int z0 = nt * 8 + 2 * lc;
                    #pragma unroll
                    for (int zz = 0; zz < 2; ++zz) {
                        int z = z0 + zz;
                        if (z < ZD) {
                            if (gl < NG) pbase[(size_t)z * NG + gl] = acc[m][i][zz];
                            if (gh < NG) pbase[(size_t)z * NG + gh] = acc[m][i][2 + zz];
                        } else if (z == ZD) {
                            if (gl < NG) dbase[gl] = acc[m][i][zz];
                            if (gh < NG) dbase[gh] = acc[m][i][2 + zz];
                        }
                    }
                }
            }
        }
    }
}

// ---------------- reduce: sum splits, divide, emit (z, gene) ----------------
__global__ void reduce_kernel(float* __restrict__ out) {
    int i4 = blockIdx.x * blockDim.x + threadIdx.x;
    int base = i4 * 4;
    if (base >= ZD * NG) return;
    int gidx = base % NG;
    float4 num = make_float4(0.f, 0.f, 0.f, 0.f);
    float4 den = make_float4(0.f, 0.f, 0.f, 0.f);
    #pragma unroll
    for (int s = 0; s < NSPLIT; ++s) {
        float4 n = *reinterpret_cast<const float4*>(g_pnum + (size_t)s * (ZD * NG) + base);
        float4 d = *reinterpret_cast<const float4*>(g_pden + s * NG + gidx);
        num.x += n.x; num.y += n.y; num.z += n.z; num.w += n.w;
        den.x += d.x; den.y += d.y; den.z += d.z; den.w += d.w;
    }
    float4 o;
    o.x = num.x / den.x; o.y = num.y / den.y; o.z = num.z / den.z; o.w = num.w / den.w;
    *reinterpret_cast<float4*>(out + base) = o;
}

// ---------------- launch ----------------
extern "C" void kernel_launch(void* const* d_in, const int* in_sizes, int n_in,
                              void* d_out, int out_size) {
    const float* rawZ   = (const float*)d_in[0];
    const float* genZ   = (const float*)d_in[1];
    const float* Grep   = (const float*)d_in[2];
    const float* gumbel = (const float*)d_in[3];
    const float* Wz1 = (const float*)d_in[4];
    const float* bz1 = (const float*)d_in[5];
    const float* Wz2 = (const float*)d_in[6];
    const float* bz2 = (const float*)d_in[7];
    const float* Wg1 = (const float*)d_in[8];
    const float* bg1 = (const float*)d_in[9];
    const float* Wg2 = (const float*)d_in[10];
    const float* bg2 = (const float*)d_in[11];
    float* out = (float*)d_out;

    cudaFuncSetAttribute(decoder_main_kernel,
                         cudaFuncAttributeMaxDynamicSharedMemorySize, SMEM_MAIN);

    key_mlp_kernel<<<NC / 32, 256>>>(rawZ, Wz1, bz1, Wz2, bz2);
    query_mlp_kernel<<<(NG + 63) / 64, 64>>>(Grep, Wg1, bg1, Wg2, bg2);

    dim3 grid((NG + GT - 1) / GT, NSPLIT);
    decoder_main_kernel<<<grid, THREADS, SMEM_MAIN>>>(gumbel, genZ);

    reduce_kernel<<<(ZD * NG / 4 + 255) / 256, 256>>>(out);
}

// round 9
// speedup vs baseline: 2.9495x; 1.1575x over previous
#include <cuda_runtime.h>
#include <math.h>
#include <stdint.h>

#define NG 10000      // genes
#define NC 8192       // cells
#define ZD 100        // z dim
#define KD 32         // key dim
#define HD 256        // hidden dim (key MLP)
#define GT 256        // genes per CTA (= M)
#define CT 64         // cells per chunk
#define NSPLIT 32     // cell splits
#define CPC (NC / NSPLIT)        // 256 cells per CTA
#define NCHUNK (CPC / CT)        // 4 chunks
#define THREADS 512

#define KSTR 36       // Ks row stride (floats)
#define VSTR 68       // Vs row stride (z-major: [z][cell])
#define GSTR 68       // Gs row stride
#define PSTR 68       // Ps row stride

// log2(e), log2(e)/sqrt(32)
#define L2E 1.4426950408889634f
#define SCALE_S 0.25503482f

typedef unsigned long long u64;

__device__ __forceinline__ uint32_t smem_u32(const void* p) {
    uint32_t a;
    asm("{ .reg .u64 t; cvta.to.shared.u64 t, %1; cvt.u32.u64 %0, t; }" : "=r"(a) : "l"(p));
    return a;
}

__device__ __forceinline__ float to_tf32(float x) {
    uint32_t r;
    asm("cvt.rna.tf32.f32 %0, %1;" : "=r"(r) : "f"(x));
    return __uint_as_float(r);
}

__device__ __forceinline__ void ldmx4(uint32_t* r, uint32_t addr) {
    asm volatile("ldmatrix.sync.aligned.m8n8.x4.shared.b16 {%0,%1,%2,%3}, [%4];"
        : "=r"(r[0]), "=r"(r[1]), "=r"(r[2]), "=r"(r[3]) : "r"(addr));
}
__device__ __forceinline__ void ldmx2(uint32_t* r, uint32_t addr) {
    asm volatile("ldmatrix.sync.aligned.m8n8.x2.shared.b16 {%0,%1}, [%2];"
        : "=r"(r[0]), "=r"(r[1]) : "r"(addr));
}

// m16n8k8 tf32 mma, C=D accum
__device__ __forceinline__ void mma_tf32(float* c,
                                         uint32_t a0, uint32_t a1, uint32_t a2, uint32_t a3,
                                         uint32_t b0, uint32_t b1) {
    asm volatile(
        "mma.sync.aligned.m16n8k8.row.col.f32.tf32.tf32.f32 "
        "{%0,%1,%2,%3}, {%4,%5,%6,%7}, {%8,%9}, {%0,%1,%2,%3};"
        : "+f"(c[0]), "+f"(c[1]), "+f"(c[2]), "+f"(c[3])
        : "r"(a0), "r"(a1), "r"(a2), "r"(a3), "r"(b0), "r"(b1));
}

__device__ __forceinline__ float gelu_exact(float x) {
    return 0.5f * x * (1.0f + erff(x * 0.70710678118654752440f));
}

// ---------------- device scratch ----------------
__device__ __align__(16) float g_key[NC * KD];           // [cell][k]
__device__ __align__(16) float g_query[NG * KD];         // [gene][k]
__device__ __align__(16) float g_pnum[NSPLIT * ZD * NG]; // [split][z][gene]
__device__ __align__(16) float g_pden[NSPLIT * NG];      // [split][gene]
__device__ __align__(16) float g_densum[NG];

// ---------------- kernel A: key MLP (cells) ----------------
__global__ void __launch_bounds__(256, 1)
key_mlp_kernel(const float* __restrict__ rawZ,
               const float* __restrict__ Wz1, const float* __restrict__ bz1,
               const float* __restrict__ Wz2, const float* __restrict__ bz2) {
    __shared__ float Zs[ZD * 32];
    __shared__ float Hs[32 * HD];
    int tid = threadIdx.x;
    int c0 = blockIdx.x * 32;

    for (int idx = tid; idx < ZD * 32; idx += 256) {
        int k = idx >> 5, cc = idx & 31;
        Zs[idx] = rawZ[(size_t)k * NC + c0 + cc];
    }
    __syncthreads();
    {
        int h = tid;
        float w[ZD];
        #pragma unroll
        for (int k = 0; k < ZD; ++k) w[k] = Wz1[k * HD + h];
        float b = bz1[h];
        for (int cc = 0; cc < 32; ++cc) {
            float a = b;
            #pragma unroll
            for (int k = 0; k < ZD; ++k) a = fmaf(Zs[k * 32 + cc], w[k], a);
            Hs[cc * HD + h] = gelu_exact(a);
        }
    }
    __syncthreads();
    for (int idx = tid; idx < 32 * KD; idx += 256) {
        int cc = idx >> 5, kk = idx & 31;
        float a = bz2[kk];
        #pragma unroll 8
        for (int h = 0; h < HD; ++h) a = fmaf(Hs[cc * HD + h], Wz2[h * KD + kk], a);
        g_key[(size_t)(c0 + cc) * KD + kk] = a;
    }
}

// ---------------- kernel B: query MLP (genes) ----------------
__global__ void query_mlp_kernel(const float* __restrict__ Grep,
                                 const float* __restrict__ Wg1, const float* __restrict__ bg1,
                                 const float* __restrict__ Wg2, const float* __restrict__ bg2) {
    __shared__ float Gs[64 * 101];
    __shared__ float W1s[100 * 32];
    __shared__ float W2s[32 * 32];
    __shared__ float b1s[32], b2s[32];
    int tid = threadIdx.x;
    int g0 = blockIdx.x * 64;
    int valid = min(64, NG - g0);

    for (int idx = tid; idx < valid * 100; idx += 64) {
        int r = idx / 100, c = idx - r * 100;
        Gs[r * 101 + c] = Grep[(size_t)g0 * 100 + idx];
    }
    for (int idx = tid; idx < 100 * 32; idx += 64) W1s[idx] = Wg1[idx];
    for (int idx = tid; idx < 32 * 32; idx += 64) W2s[idx] = Wg2[idx];
    if (tid < 32) { b1s[tid] = bg1[tid]; b2s[tid] = bg2[tid]; }
    __syncthreads();

    if (tid < valid) {
        float hid[32];
        #pragma unroll
        for (int j = 0; j < 32; ++j) hid[j] = b1s[j];
        for (int k = 0; k < 100; ++k) {
            float gv = Gs[tid * 101 + k];
            #pragma unroll
            for (int j = 0; j < 32; ++j) hid[j] = fmaf(gv, W1s[k * 32 + j], hid[j]);
        }
        #pragma unroll
        for (int j = 0; j < 32; ++j) hid[j] = gelu_exact(hid[j]);
        int g = g0 + tid;
        #pragma unroll 4
        for (int kk = 0; kk < 32; ++kk) {
            float a = b2s[kk];
            #pragma unroll
            for (int j = 0; j < 32; ++j) a = fmaf(hid[j], W2s[j * 32 + kk], a);
            g_query[(size_t)g * KD + kk] = a;
        }
    }
}

// ---------------- main fused kernel ----------------
// smem (floats)
#define KS_OFF 0
#define VS_OFF (CT * KSTR)                       // 2304
#define GS_OFF (VS_OFF + 104 * VSTR)             // 9376
#define PS_OFF (GS_OFF + GT * GSTR)              // 26784
#define SMEM_FLOATS (PS_OFF + GT * PSTR)         // 44192
#define SMEM_MAIN (SMEM_FLOATS * 4)              // 176768 B

__global__ void __launch_bounds__(THREADS, 1)
decoder_main_kernel(const float* __restrict__ gumbel,
                    const float* __restrict__ genZ) {
    extern __shared__ float smem[];
    float* Ks = smem + KS_OFF;
    float* Vs = smem + VS_OFF;   // [z][cell]
    float* Gs = smem + GS_OFF;   // [gene][cell]
    float* Ps = smem + PS_OFF;   // [gene][cell]

    int tid = threadIdx.x;
    int wid = tid >> 5;
    int lane = tid & 31;
    int split = blockIdx.y;
    int gbase = blockIdx.x * GT;

    int lr = lane >> 2;             // fragment row group
    int lc = lane & 3;              // fragment col group

    // S identity: warp = one m16 tile (16 warps = 256 genes)
    int arowS = wid * 16 + lr;

    // PV identity: 8 m-groups (2 m-tiles each) x 2 n-groups
    int mg = wid & 7;
    int ngrp = wid >> 3;
    int ntbase = ngrp * 7;
    int ntcnt = ngrp ? 6 : 7;

    // ldmatrix lane components
    int lt = lane >> 3, lrow = lane & 7;
    uint32_t ks_b = smem_u32(Ks);
    uint32_t vs_b = smem_u32(Vs);
    uint32_t ps_b = smem_u32(Ps);
    // S K-frag x4: tiles {c0,c4,c8,c12} x rows(cells)
    uint32_t k_lane = ks_b + (uint32_t)((lrow * KSTR + lt * 4) * 4);
    // PV A x4: tiles {r0c0, r8c0, r0c4, r8c4}
    uint32_t a_lane = ps_b + (uint32_t)(((((lt & 1) * 8) + lrow) * PSTR + (lt >> 1) * 4) * 4);
    uint32_t aA0 = a_lane + (uint32_t)((mg * 32) * PSTR * 4);
    uint32_t aA1 = aA0 + (uint32_t)(16 * PSTR * 4);
    // PV B x4 (nt pair): tiles {nta c0, nta c4, ntb c0, ntb c4}; rows = z
    uint32_t b_lane = vs_b + (uint32_t)(((((lt >> 1) * 8) + lrow) * VSTR + (lt & 1) * 4) * 4);
    // PV B x2 (single nt, ngrp0 only): tiles {c0, c4}
    uint32_t b2_lane = vs_b + (uint32_t)((lrow * VSTR + (lt & 1) * 4) * 4)
                     + (uint32_t)(((ntbase + 6) * 8) * VSTR * 4);

    // ---- Q fragments in registers, loaded once (tf32) ----
    uint32_t qf[4][4];
    {
        int gq0 = min(gbase + arowS, NG - 1);
        int gq1 = min(gbase + arowS + 8, NG - 1);
        const float* q0 = g_query + (size_t)gq0 * KD;
        const float* q1 = g_query + (size_t)gq1 * KD;
        #pragma unroll
        for (int k8 = 0; k8 < 4; ++k8) {
            int k = k8 * 8 + lc;
            qf[k8][0] = __float_as_uint(to_tf32(q0[k]));
            qf[k8][1] = __float_as_uint(to_tf32(q1[k]));
            qf[k8][2] = __float_as_uint(to_tf32(q0[k + 4]));
            qf[k8][3] = __float_as_uint(to_tf32(q1[k + 4]));
        }
    }

    float acc[2][7][4];
    #pragma unroll
    for (int m = 0; m < 2; ++m)
        #pragma unroll
        for (int i = 0; i < 7; ++i) {
            acc[m][i][0] = 0.f; acc[m][i][1] = 0.f;
            acc[m][i][2] = 0.f; acc[m][i][3] = 0.f;
        }

    for (int t = 0; t < NCHUNK; ++t) {
        int cbase = split * CPC + t * CT;
        __syncthreads();   // protect smem reuse from previous chunk's readers

        // ---- stage K tile (tf32, [cell][k] stride 36) ----
        #pragma unroll
        for (int i = 0; i < (CT * KD) / THREADS; ++i) {
            int idx = tid + i * THREADS;
            int c = idx >> 5, k = idx & 31;
            Ks[c * KSTR + k] = to_tf32(g_key[(size_t)(cbase + c) * KD + k]);
        }
        // ---- stage V_ext z-major (tf32): Vs[z][cell], 104 rows x 16 float4 ----
        #pragma unroll
        for (int i = 0; i < 4; ++i) {
            int idx = tid + i * THREADS;
            if (idx < 104 * 16) {
                int z = idx >> 4, c4 = idx & 15;
                float4 v;
                if (z < ZD) {
                    v = *reinterpret_cast<const float4*>(genZ + (size_t)z * NC + cbase + c4 * 4);
                    v.x = to_tf32(v.x); v.y = to_tf32(v.y);
                    v.z = to_tf32(v.z); v.w = to_tf32(v.w);
                } else if (z == ZD) {
                    v = make_float4(1.f, 1.f, 1.f, 1.f);
                } else {
                    v = make_float4(0.f, 0.f, 0.f, 0.f);
                }
                *reinterpret_cast<float4*>(Vs + z * VSTR + c4 * 4) = v;
            }
        }
        // ---- stage gumbel tile coalesced, prescaled by log2(e) ----
        #pragma unroll
        for (int i = 0; i < (GT * (CT / 4)) / THREADS; ++i) {
            int idx = tid + i * THREADS;
            int gr = idx >> 4, c4 = idx & 15;
            int grow = min(gbase + gr, NG - 1);
            float4 v = *reinterpret_cast<const float4*>(
                gumbel + (size_t)grow * NC + cbase + c4 * 4);
            v.x *= L2E; v.y *= L2E; v.z *= L2E; v.w *= L2E;
            *reinterpret_cast<float4*>(Gs + gr * GSTR + c4 * 4) = v;
        }
        __syncthreads();

        // ---- phase S: ldmatrix K frags; exp + scatter immediately ----
        #pragma unroll
        for (int nt = 0; nt < CT / 8; ++nt) {
            uint32_t kb[8];
            uint32_t ka = k_lane + (uint32_t)(nt * 8 * KSTR * 4);
            ldmx4(kb, ka);
            ldmx4(kb + 4, ka + 64);
            float sacc[4] = {0.f, 0.f, 0.f, 0.f};
            mma_tf32(sacc, qf[0][0], qf[0][1], qf[0][2], qf[0][3], kb[0], kb[1]);
            mma_tf32(sacc, qf[1][0], qf[1][1], qf[1][2], qf[1][3], kb[2], kb[3]);
            mma_tf32(sacc, qf[2][0], qf[2][1], qf[2][2], qf[2][3], kb[4], kb[5]);
            mma_tf32(sacc, qf[3][0], qf[3][1], qf[3][2], qf[3][3], kb[6], kb[7]);
            int c0 = nt * 8 + 2 * lc;
            float2 gA = *reinterpret_cast<const float2*>(Gs + arowS * GSTR + c0);
            float2 gB = *reinterpret_cast<const float2*>(Gs + (arowS + 8) * GSTR + c0);
            float2 pA, pB;
            pA.x = to_tf32(exp2f(fmaf(sacc[0], SCALE_S, gA.x)));
            pA.y = to_tf32(exp2f(fmaf(sacc[1], SCALE_S, gA.y)));
            pB.x = to_tf32(exp2f(fmaf(sacc[2], SCALE_S, gB.x)));
            pB.y = to_tf32(exp2f(fmaf(sacc[3], SCALE_S, gB.y)));
            *reinterpret_cast<float2*>(Ps + arowS * PSTR + c0) = pA;
            *reinterpret_cast<float2*>(Ps + (arowS + 8) * PSTR + c0) = pB;
        }
        __syncthreads();

        // ---- phase PV: D += P @ V_ext^T via ldmatrix + mma ----
        #pragma unroll
        for (int k8 = 0; k8 < CT / 8; ++k8) {
            uint32_t k0b = (uint32_t)(k8 * 8 * 4);
            uint32_t af0[4], af1[4];
            ldmx4(af0, aA0 + k0b);
            ldmx4(af1, aA1 + k0b);
            #pragma unroll
            for (int p = 0; p < 3; ++p) {
                uint32_t bf[4];
                ldmx4(bf, b_lane + (uint32_t)(((ntbase + 2 * p) * 8) * VSTR * 4) + k0b);
                mma_tf32(acc[0][2 * p],     af0[0], af0[1], af0[2], af0[3], bf[0], bf[1]);
                mma_tf32(acc[1][2 * p],     af1[0], af1[1], af1[2], af1[3], bf[0], bf[1]);
                mma_tf32(acc[0][2 * p + 1], af0[0], af0[1], af0[2], af0[3], bf[2], bf[3]);
                mma_tf32(acc[1][2 * p + 1], af1[0], af1[1], af1[2], af1[3], bf[2], bf[3]);
            }
            if (ngrp == 0) {
                uint32_t bf2[2];
                ldmx2(bf2, b2_lane + k0b);
                mma_tf32(acc[0][6], af0[0], af0[1], af0[2], af0[3], bf2[0], bf2[1]);
                mma_tf32(acc[1][6], af1[0], af1[1], af1[2], af1[3], bf2[0], bf2[1]);
            }
        }
    }

    // ---- epilogue: scatter D fragments to split partials ----
    {
        float* pbase = g_pnum + (size_t)split * (ZD * NG);
        float* dbase = g_pden + split * NG;
        #pragma unroll
        for (int m = 0; m < 2; ++m) {
            int gl = gbase + mg * 32 + lr + m * 16;
            int gh = gl + 8;
            #pragma unroll
            for (int i = 0; i < 7; ++i) {
                if (i < ntcnt) {
                    int nt = ntbase + i;
                    int z0 = nt * 8 + 2 * lc;
                    #pragma unroll
                    for (int zz = 0; zz < 2; ++zz) {
                        int z = z0 + zz;
                        if (z < ZD) {
                            if (gl < NG) pbase[(size_t)z * NG + gl] = acc[m][i][zz];
                            if (gh < NG) pbase[(size_t)z * NG + gh] = acc[m][i][2 + zz];
                        } else if (z == ZD) {
                            if (gl < NG) dbase[gl] = acc[m][i][zz];
                            if (gh < NG) dbase[gh] = acc[m][i][2 + zz];
                        }
                    }
                }
            }
        }
    }
}

// ---------------- den pre-reduction: sum splits once ----------------
__global__ void densum_kernel() {
    int i4 = blockIdx.x * blockDim.x + threadIdx.x;
    int base = i4 * 4;
    if (base >= NG) return;
    float4 d = make_float4(0.f, 0.f, 0.f, 0.f);
    #pragma unroll
    for (int s = 0; s < NSPLIT; ++s) {
        float4 x = *reinterpret_cast<const float4*>(g_pden + s * NG + base);
        d.x += x.x; d.y += x.y; d.z += x.z; d.w += x.w;
    }
    *reinterpret_cast<float4*>(g_densum + base) = d;
}

// ---------------- reduce: sum num splits, divide by densum ----------------
__global__ void reduce_kernel(float* __restrict__ out) {
    int i4 = blockIdx.x * blockDim.x + threadIdx.x;
    int base = i4 * 4;
    if (base >= ZD * NG) return;
    int gidx = base % NG;
    float4 num = make_float4(0.f, 0.f, 0.f, 0.f);
    #pragma unroll
    for (int s = 0; s < NSPLIT; ++s) {
        float4 n = *reinterpret_cast<const float4*>(g_pnum + (size_t)s * (ZD * NG) + base);
        num.x += n.x; num.y += n.y; num.z += n.z; num.w += n.w;
    }
    float4 den = *reinterpret_cast<const float4*>(g_densum + gidx);
    float4 o;
    o.x = num.x / den.x; o.y = num.y / den.y; o.z = num.z / den.z; o.w = num.w / den.w;
    *reinterpret_cast<float4*>(out + base) = o;
}

// ---------------- launch ----------------
extern "C" void kernel_launch(void* const* d_in, const int* in_sizes, int n_in,
                              void* d_out, int out_size) {
    const float* rawZ   = (const float*)d_in[0];
    const float* genZ   = (const float*)d_in[1];
    const float* Grep   = (const float*)d_in[2];
    const float* gumbel = (const float*)d_in[3];
    const float* Wz1 = (const float*)d_in[4];
    const float* bz1 = (const float*)d_in[5];
    const float* Wz2 = (const float*)d_in[6];
    const float* bz2 = (const float*)d_in[7];
    const float* Wg1 = (const float*)d_in[8];
    const float* bg1 = (const float*)d_in[9];
    const float* Wg2 = (const float*)d_in[10];
    const float* bg2 = (const float*)d_in[11];
    float* out = (float*)d_out;

    cudaFuncSetAttribute(decoder_main_kernel,
                         cudaFuncAttributeMaxDynamicSharedMemorySize, SMEM_MAIN);

    key_mlp_kernel<<<NC / 32, 256>>>(rawZ, Wz1, bz1, Wz2, bz2);
    query_mlp_kernel<<<(NG + 63) / 64, 64>>>(Grep, Wg1, bg1, Wg2, bg2);

    dim3 grid((NG + GT - 1) / GT, NSPLIT);
    decoder_main_kernel<<<grid, THREADS, SMEM_MAIN>>>(gumbel, genZ);

    densum_kernel<<<(NG / 4 + 255) / 256, 256>>>();
    reduce_kernel<<<(ZD * NG / 4 + 255) / 256, 256>>>(out);
}

// round 10
// speedup vs baseline: 3.3906x; 1.1496x over previous
#include <cuda_runtime.h>
#include <math.h>
#include <stdint.h>

#define NG 10000      // genes
#define NC 8192       // cells
#define ZD 100        // z dim
#define KD 32         // key dim
#define HD 256        // hidden dim (key MLP)
#define GT 256        // genes per CTA (= M)
#define CT 64         // cells per chunk
#define NSPLIT 32     // cell splits
#define CPC (NC / NSPLIT)        // 256 cells per CTA
#define NCHUNK (CPC / CT)        // 4 chunks
#define THREADS 512

#define KSTR 36       // Ks row stride (floats)
#define VSTR 68       // Vs row stride (z-major: [z][cell])
#define GSTR 68       // Gs row stride
#define PSTR 68       // Ps row stride

// log2(e), log2(e)/sqrt(32)
#define L2E 1.4426950408889634f
#define SCALE_S 0.25503482f

typedef unsigned long long u64;

__device__ __forceinline__ uint32_t smem_u32(const void* p) {
    uint32_t a;
    asm("{ .reg .u64 t; cvta.to.shared.u64 t, %1; cvt.u32.u64 %0, t; }" : "=r"(a) : "l"(p));
    return a;
}

__device__ __forceinline__ float to_tf32(float x) {
    uint32_t r;
    asm("cvt.rna.tf32.f32 %0, %1;" : "=r"(r) : "f"(x));
    return __uint_as_float(r);
}

__device__ __forceinline__ void cpa16(uint32_t dst, const void* src) {
    asm volatile("cp.async.cg.shared.global [%0], [%1], 16;" :: "r"(dst), "l"(src));
}
#define CPA_COMMIT() asm volatile("cp.async.commit_group;" ::: "memory")
#define CPA_WAIT0()  asm volatile("cp.async.wait_group 0;" ::: "memory")

__device__ __forceinline__ void ldmx4(uint32_t* r, uint32_t addr) {
    asm volatile("ldmatrix.sync.aligned.m8n8.x4.shared.b16 {%0,%1,%2,%3}, [%4];"
        : "=r"(r[0]), "=r"(r[1]), "=r"(r[2]), "=r"(r[3]) : "r"(addr));
}
__device__ __forceinline__ void ldmx2(uint32_t* r, uint32_t addr) {
    asm volatile("ldmatrix.sync.aligned.m8n8.x2.shared.b16 {%0,%1}, [%2];"
        : "=r"(r[0]), "=r"(r[1]) : "r"(addr));
}

// m16n8k8 tf32 mma, C=D accum
__device__ __forceinline__ void mma_tf32(float* c,
                                         uint32_t a0, uint32_t a1, uint32_t a2, uint32_t a3,
                                         uint32_t b0, uint32_t b1) {
    asm volatile(
        "mma.sync.aligned.m16n8k8.row.col.f32.tf32.tf32.f32 "
        "{%0,%1,%2,%3}, {%4,%5,%6,%7}, {%8,%9}, {%0,%1,%2,%3};"
        : "+f"(c[0]), "+f"(c[1]), "+f"(c[2]), "+f"(c[3])
        : "r"(a0), "r"(a1), "r"(a2), "r"(a3), "r"(b0), "r"(b1));
}

__device__ __forceinline__ float gelu_exact(float x) {
    return 0.5f * x * (1.0f + erff(x * 0.70710678118654752440f));
}

// ---------------- device scratch ----------------
__device__ __align__(16) float g_key[NC * KD];           // [cell][k]  (tf32-rounded)
__device__ __align__(16) float g_query[NG * KD];         // [gene][k]
__device__ __align__(16) float g_pnum[NSPLIT * ZD * NG]; // [split][z][gene]
__device__ __align__(16) float g_pden[NSPLIT * NG];      // [split][gene]
__device__ __align__(16) float g_densum[NG];

// ---------------- kernel A: key MLP (cells); emits tf32-rounded keys ----------------
__global__ void __launch_bounds__(256, 1)
key_mlp_kernel(const float* __restrict__ rawZ,
               const float* __restrict__ Wz1, const float* __restrict__ bz1,
               const float* __restrict__ Wz2, const float* __restrict__ bz2) {
    __shared__ float Zs[ZD * 32];
    __shared__ float Hs[32 * HD];
    int tid = threadIdx.x;
    int c0 = blockIdx.x * 32;

    for (int idx = tid; idx < ZD * 32; idx += 256) {
        int k = idx >> 5, cc = idx & 31;
        Zs[idx] = rawZ[(size_t)k * NC + c0 + cc];
    }
    __syncthreads();
    {
        int h = tid;
        float w[ZD];
        #pragma unroll
        for (int k = 0; k < ZD; ++k) w[k] = Wz1[k * HD + h];
        float b = bz1[h];
        for (int cc = 0; cc < 32; ++cc) {
            float a = b;
            #pragma unroll
            for (int k = 0; k < ZD; ++k) a = fmaf(Zs[k * 32 + cc], w[k], a);
            Hs[cc * HD + h] = gelu_exact(a);
        }
    }
    __syncthreads();
    for (int idx = tid; idx < 32 * KD; idx += 256) {
        int cc = idx >> 5, kk = idx & 31;
        float a = bz2[kk];
        #pragma unroll 8
        for (int h = 0; h < HD; ++h) a = fmaf(Hs[cc * HD + h], Wz2[h * KD + kk], a);
        g_key[(size_t)(c0 + cc) * KD + kk] = to_tf32(a);
    }
}

// ---------------- kernel B: query MLP (genes) ----------------
__global__ void query_mlp_kernel(const float* __restrict__ Grep,
                                 const float* __restrict__ Wg1, const float* __restrict__ bg1,
                                 const float* __restrict__ Wg2, const float* __restrict__ bg2) {
    __shared__ float Gs[64 * 101];
    __shared__ float W1s[100 * 32];
    __shared__ float W2s[32 * 32];
    __shared__ float b1s[32], b2s[32];
    int tid = threadIdx.x;
    int g0 = blockIdx.x * 64;
    int valid = min(64, NG - g0);

    for (int idx = tid; idx < valid * 100; idx += 64) {
        int r = idx / 100, c = idx - r * 100;
        Gs[r * 101 + c] = Grep[(size_t)g0 * 100 + idx];
    }
    for (int idx = tid; idx < 100 * 32; idx += 64) W1s[idx] = Wg1[idx];
    for (int idx = tid; idx < 32 * 32; idx += 64) W2s[idx] = Wg2[idx];
    if (tid < 32) { b1s[tid] = bg1[tid]; b2s[tid] = bg2[tid]; }
    __syncthreads();

    if (tid < valid) {
        float hid[32];
        #pragma unroll
        for (int j = 0; j < 32; ++j) hid[j] = b1s[j];
        for (int k = 0; k < 100; ++k) {
            float gv = Gs[tid * 101 + k];
            #pragma unroll
            for (int j = 0; j < 32; ++j) hid[j] = fmaf(gv, W1s[k * 32 + j], hid[j]);
        }
        #pragma unroll
        for (int j = 0; j < 32; ++j) hid[j] = gelu_exact(hid[j]);
        int g = g0 + tid;
        #pragma unroll 4
        for (int kk = 0; kk < 32; ++kk) {
            float a = b2s[kk];
            #pragma unroll
            for (int j = 0; j < 32; ++j) a = fmaf(hid[j], W2s[j * 32 + kk], a);
            g_query[(size_t)g * KD + kk] = a;
        }
    }
}

// ---------------- main fused kernel ----------------
// smem (floats)
#define KS_OFF 0
#define VBUF (104 * VSTR)                        // 7072 floats per V buffer
#define VS_OFF (CT * KSTR)                       // 2304
#define GS_OFF (VS_OFF + 2 * VBUF)               // 16448
#define PS_OFF (GS_OFF + GT * GSTR)              // 33856
#define SMEM_FLOATS (PS_OFF + GT * PSTR)         // 51264
#define SMEM_MAIN (SMEM_FLOATS * 4)              // 205056 B

__global__ void __launch_bounds__(THREADS, 1)
decoder_main_kernel(const float* __restrict__ gumbel,
                    const float* __restrict__ genZ) {
    extern __shared__ float smem[];
    float* Ks = smem + KS_OFF;
    float* Vs = smem + VS_OFF;   // [buf][z][cell]
    float* Gs = smem + GS_OFF;   // [gene][cell] raw gumbel
    float* Ps = smem + PS_OFF;   // [gene][cell]

    int tid = threadIdx.x;
    int wid = tid >> 5;
    int lane = tid & 31;
    int split = blockIdx.y;
    int gbase = blockIdx.x * GT;

    int lr = lane >> 2;
    int lc = lane & 3;

    int arowS = wid * 16 + lr;      // S identity
    int mg = wid & 7;               // PV m-group
    int ngrp = wid >> 3;            // PV n-group
    int ntbase = ngrp * 7;
    int ntcnt = ngrp ? 6 : 7;

    // ldmatrix lane components
    int lt = lane >> 3, lrow = lane & 7;
    uint32_t ks_b = smem_u32(Ks);
    uint32_t vs_b = smem_u32(Vs);
    uint32_t gs_b = smem_u32(Gs);
    uint32_t ps_b = smem_u32(Ps);
    uint32_t k_lane = ks_b + (uint32_t)((lrow * KSTR + lt * 4) * 4);
    uint32_t a_lane = ps_b + (uint32_t)(((((lt & 1) * 8) + lrow) * PSTR + (lt >> 1) * 4) * 4);
    uint32_t aA0 = a_lane + (uint32_t)((mg * 32) * PSTR * 4);
    uint32_t aA1 = aA0 + (uint32_t)(16 * PSTR * 4);
    uint32_t b_lane0 = vs_b + (uint32_t)(((((lt >> 1) * 8) + lrow) * VSTR + (lt & 1) * 4) * 4);
    uint32_t b2_lane0 = vs_b + (uint32_t)((lrow * VSTR + (lt & 1) * 4) * 4)
                      + (uint32_t)(((ntbase + 6) * 8) * VSTR * 4);

    // staging lane assignments
    int kc = tid >> 3, kq = tid & 7;                 // K: 512 float4
    uint32_t k_dst = ks_b + (uint32_t)((kc * KSTR + kq * 4) * 4);

    // ---- Q fragments in registers, loaded once (tf32) ----
    uint32_t qf[4][4];
    {
        int gq0 = min(gbase + arowS, NG - 1);
        int gq1 = min(gbase + arowS + 8, NG - 1);
        const float* q0 = g_query + (size_t)gq0 * KD;
        const float* q1 = g_query + (size_t)gq1 * KD;
        #pragma unroll
        for (int k8 = 0; k8 < 4; ++k8) {
            int k = k8 * 8 + lc;
            qf[k8][0] = __float_as_uint(to_tf32(q0[k]));
            qf[k8][1] = __float_as_uint(to_tf32(q1[k]));
            qf[k8][2] = __float_as_uint(to_tf32(q0[k + 4]));
            qf[k8][3] = __float_as_uint(to_tf32(q1[k + 4]));
        }
    }

    // ---- staging helpers (lambdas) ----
    auto stage_K = [&](int cbase) {
        cpa16(k_dst, g_key + (size_t)(cbase + kc) * KD + kq * 4);
    };
    auto stage_V = [&](int buf, int cbase) {
        #pragma unroll
        for (int i = 0; i < 4; ++i) {
            int idx = tid + i * THREADS;
            if (idx < ZD * 16) {
                int z = idx >> 4, c4 = idx & 15;
                cpa16(vs_b + (uint32_t)((buf * VBUF + z * VSTR + c4 * 4) * 4),
                      genZ + (size_t)z * NC + cbase + c4 * 4);
            }
        }
    };
    auto stage_G = [&](int cbase) {
        #pragma unroll
        for (int i = 0; i < 8; ++i) {
            int idx = tid + i * THREADS;
            int gr = idx >> 4, c4 = idx & 15;
            int grow = min(gbase + gr, NG - 1);
            cpa16(gs_b + (uint32_t)((gr * GSTR + c4 * 4) * 4),
                  gumbel + (size_t)grow * NC + cbase + c4 * 4);
        }
    };

    float acc[2][7][4];
    #pragma unroll
    for (int m = 0; m < 2; ++m)
        #pragma unroll
        for (int i = 0; i < 7; ++i) {
            acc[m][i][0] = 0.f; acc[m][i][1] = 0.f;
            acc[m][i][2] = 0.f; acc[m][i][3] = 0.f;
        }

    // ---- prologue: stage chunk 0, fill V pad rows (both buffers, once) ----
    int cbase0 = split * CPC;
    stage_K(cbase0);
    stage_V(0, cbase0);
    stage_G(cbase0);
    CPA_COMMIT();
    // pad rows z=100 (ones) and 101..103 (zeros), both buffers
    if (tid < 128) {
        int buf = tid >> 6, zr = (tid >> 4) & 3, c4 = tid & 15;
        float4 v = (zr == 0) ? make_float4(1.f, 1.f, 1.f, 1.f)
                             : make_float4(0.f, 0.f, 0.f, 0.f);
        *reinterpret_cast<float4*>(Vs + buf * VBUF + (ZD + zr) * VSTR + c4 * 4) = v;
    }
    CPA_WAIT0();
    __syncthreads();

    for (int t = 0; t < NCHUNK; ++t) {
        int buf = t & 1;

        // ---- phase S: ldmatrix K frags; exp + scatter to Ps ----
        #pragma unroll
        for (int nt = 0; nt < CT / 8; ++nt) {
            uint32_t kb[8];
            uint32_t ka = k_lane + (uint32_t)(nt * 8 * KSTR * 4);
            ldmx4(kb, ka);
            ldmx4(kb + 4, ka + 64);
            float sacc[4] = {0.f, 0.f, 0.f, 0.f};
            mma_tf32(sacc, qf[0][0], qf[0][1], qf[0][2], qf[0][3], kb[0], kb[1]);
            mma_tf32(sacc, qf[1][0], qf[1][1], qf[1][2], qf[1][3], kb[2], kb[3]);
            mma_tf32(sacc, qf[2][0], qf[2][1], qf[2][2], qf[2][3], kb[4], kb[5]);
            mma_tf32(sacc, qf[3][0], qf[3][1], qf[3][2], qf[3][3], kb[6], kb[7]);
            int c0 = nt * 8 + 2 * lc;
            float2 gA = *reinterpret_cast<const float2*>(Gs + arowS * GSTR + c0);
            float2 gB = *reinterpret_cast<const float2*>(Gs + (arowS + 8) * GSTR + c0);
            float2 pA, pB;
            pA.x = exp2f(fmaf(gA.x, L2E, sacc[0] * SCALE_S));
            pA.y = exp2f(fmaf(gA.y, L2E, sacc[1] * SCALE_S));
            pB.x = exp2f(fmaf(gB.x, L2E, sacc[2] * SCALE_S));
            pB.y = exp2f(fmaf(gB.y, L2E, sacc[3] * SCALE_S));
            *reinterpret_cast<float2*>(Ps + arowS * PSTR + c0) = pA;
            *reinterpret_cast<float2*>(Ps + (arowS + 8) * PSTR + c0) = pB;
        }
        __syncthreads();   // Ps ready; Ks, Gs dead

        // ---- prefetch chunk t+1 into dead K/G and other V buffer ----
        if (t + 1 < NCHUNK) {
            int cb = split * CPC + (t + 1) * CT;
            stage_K(cb);
            stage_G(cb);
            stage_V(buf ^ 1, cb);
            CPA_COMMIT();
        }

        // ---- phase PV: D += P @ V_ext^T (reads Ps, Vs[buf]) ----
        uint32_t vbo = (uint32_t)(buf * VBUF * 4);
        #pragma unroll
        for (int k8 = 0; k8 < CT / 8; ++k8) {
            uint32_t k0b = (uint32_t)(k8 * 8 * 4);
            uint32_t af0[4], af1[4];
            ldmx4(af0, aA0 + k0b);
            ldmx4(af1, aA1 + k0b);
            #pragma unroll
            for (int p = 0; p < 3; ++p) {
                uint32_t bf[4];
                ldmx4(bf, b_lane0 + vbo + (uint32_t)(((ntbase + 2 * p) * 8) * VSTR * 4) + k0b);
                mma_tf32(acc[0][2 * p],     af0[0], af0[1], af0[2], af0[3], bf[0], bf[1]);
                mma_tf32(acc[1][2 * p],     af1[0], af1[1], af1[2], af1[3], bf[0], bf[1]);
                mma_tf32(acc[0][2 * p + 1], af0[0], af0[1], af0[2], af0[3], bf[2], bf[3]);
                mma_tf32(acc[1][2 * p + 1], af1[0], af1[1], af1[2], af1[3], bf[2], bf[3]);
            }
            if (ngrp == 0) {
                uint32_t bf2[2];
                ldmx2(bf2, b2_lane0 + vbo + k0b);
                mma_tf32(acc[0][6], af0[0], af0[1], af0[2], af0[3], bf2[0], bf2[1]);
                mma_tf32(acc[1][6], af1[0], af1[1], af1[2], af1[3], bf2[0], bf2[1]);
            }
        }
        if (t + 1 < NCHUNK) { CPA_WAIT0(); }
        __syncthreads();   // PV done (Ps/V dead); prefetched K/G/V visible
    }

    // ---- epilogue: scatter D fragments to split partials ----
    {
        float* pbase = g_pnum + (size_t)split * (ZD * NG);
        float* dbase = g_pden + split * NG;
        #pragma unroll
        for (int m = 0; m < 2; ++m) {
            int gl = gbase + mg * 32 + lr + m * 16;
            int gh = gl + 8;
            #pragma unroll
            for (int i = 0; i < 7; ++i) {
                if (i < ntcnt) {
                    int nt = ntbase + i;
                    int z0 = nt * 8 + 2 * lc;
                    #pragma unroll
                    for (int zz = 0; zz < 2; ++zz) {
                        int z = z0 + zz;
                        if (z < ZD) {
                            if (gl < NG) pbase[(size_t)z * NG + gl] = acc[m][i][zz];
                            if (gh < NG) pbase[(size_t)z * NG + gh] = acc[m][i][2 + zz];
                        } else if (z == ZD) {
                            if (gl < NG) dbase[gl] = acc[m][i][zz];
                            if (gh < NG) dbase[gh] = acc[m][i][2 + zz];
                        }
                    }
                }
            }
        }
    }
}

// ---------------- den pre-reduction ----------------
__global__ void densum_kernel() {
    int i4 = blockIdx.x * blockDim.x + threadIdx.x;
    int base = i4 * 4;
    if (base >= NG) return;
    float4 d = make_float4(0.f, 0.f, 0.f, 0.f);
    #pragma unroll
    for (int s = 0; s < NSPLIT; ++s) {
        float4 x = *reinterpret_cast<const float4*>(g_pden + s * NG + base);
        d.x += x.x; d.y += x.y; d.z += x.z; d.w += x.w;
    }
    *reinterpret_cast<float4*>(g_densum + base) = d;
}

// ---------------- reduce: sum num splits, divide by densum ----------------
__global__ void reduce_kernel(float* __restrict__ out) {
    int i4 = blockIdx.x * blockDim.x + threadIdx.x;
    int base = i4 * 4;
    if (base >= ZD * NG) return;
    int gidx = base % NG;
    float4 num = make_float4(0.f, 0.f, 0.f, 0.f);
    #pragma unroll
    for (int s = 0; s < NSPLIT; ++s) {
        float4 n = *reinterpret_cast<const float4*>(g_pnum + (size_t)s * (ZD * NG) + base);
        num.x += n.x; num.y += n.y; num.z += n.z; num.w += n.w;
    }
    float4 den = *reinterpret_cast<const float4*>(g_densum + gidx);
    float4 o;
    o.x = num.x / den.x; o.y = num.y / den.y; o.z = num.z / den.z; o.w = num.w / den.w;
    *reinterpret_cast<float4*>(out + base) = o;
}

// ---------------- launch ----------------
extern "C" void kernel_launch(void* const* d_in, const int* in_sizes, int n_in,
                              void* d_out, int out_size) {
    const float* rawZ   = (const float*)d_in[0];
    const float* genZ   = (const float*)d_in[1];
    const float* Grep   = (const float*)d_in[2];
    const float* gumbel = (const float*)d_in[3];
    const float* Wz1 = (const float*)d_in[4];
    const float* bz1 = (const float*)d_in[5];
    const float* Wz2 = (const float*)d_in[6];
    const float* bz2 = (const float*)d_in[7];
    const float* Wg1 = (const float*)d_in[8];
    const float* bg1 = (const float*)d_in[9];
    const float* Wg2 = (const float*)d_in[10];
    const float* bg2 = (const float*)d_in[11];
    float* out = (float*)d_out;

    cudaFuncSetAttribute(decoder_main_kernel,
                         cudaFuncAttributeMaxDynamicSharedMemorySize, SMEM_MAIN);

    key_mlp_kernel<<<NC / 32, 256>>>(rawZ, Wz1, bz1, Wz2, bz2);
    query_mlp_kernel<<<(NG + 63) / 64, 64>>>(Grep, Wg1, bg1, Wg2, bg2);

    dim3 grid((NG + GT - 1) / GT, NSPLIT);
    decoder_main_kernel<<<grid, THREADS, SMEM_MAIN>>>(gumbel, genZ);

    densum_kernel<<<(NG / 4 + 255) / 256, 256>>>();
    reduce_kernel<<<(ZD * NG / 4 + 255) / 256, 256>>>(out);
}

// round 11
// speedup vs baseline: 3.5631x; 1.0509x over previous
#include <cuda_runtime.h>
#include <math.h>
#include <stdint.h>

#define NG 10000      // genes
#define NC 8192       // cells
#define ZD 100        // z dim
#define KD 32         // key dim
#define HD 256        // hidden dim (key MLP)
#define GT 128        // genes per CTA (= M)
#define CT 64         // cells per chunk
#define NSPLIT 16     // cell splits
#define CPC (NC / NSPLIT)        // 512 cells per CTA
#define NCHUNK (CPC / CT)        // 8 chunks
#define THREADS 512

#define KSTR 36       // Ks row stride (floats)
#define VSTR 68       // Vs row stride (z-major: [z][cell])
#define GSTR 68       // Gs row stride
#define PSTR 68       // Ps row stride

// log2(e), log2(e)/sqrt(32)
#define L2E 1.4426950408889634f
#define SCALE_S 0.25503482f

typedef unsigned long long u64;

__device__ __forceinline__ uint32_t smem_u32(const void* p) {
    uint32_t a;
    asm("{ .reg .u64 t; cvta.to.shared.u64 t, %1; cvt.u32.u64 %0, t; }" : "=r"(a) : "l"(p));
    return a;
}

__device__ __forceinline__ float to_tf32(float x) {
    uint32_t r;
    asm("cvt.rna.tf32.f32 %0, %1;" : "=r"(r) : "f"(x));
    return __uint_as_float(r);
}

__device__ __forceinline__ void cpa16(uint32_t dst, const void* src) {
    asm volatile("cp.async.cg.shared.global [%0], [%1], 16;" :: "r"(dst), "l"(src));
}
#define CPA_COMMIT() asm volatile("cp.async.commit_group;" ::: "memory")
#define CPA_WAIT0()  asm volatile("cp.async.wait_group 0;" ::: "memory")

__device__ __forceinline__ void ldmx4(uint32_t* r, uint32_t addr) {
    asm volatile("ldmatrix.sync.aligned.m8n8.x4.shared.b16 {%0,%1,%2,%3}, [%4];"
        : "=r"(r[0]), "=r"(r[1]), "=r"(r[2]), "=r"(r[3]) : "r"(addr));
}
__device__ __forceinline__ void ldmx2(uint32_t* r, uint32_t addr) {
    asm volatile("ldmatrix.sync.aligned.m8n8.x2.shared.b16 {%0,%1}, [%2];"
        : "=r"(r[0]), "=r"(r[1]) : "r"(addr));
}

// m16n8k8 tf32 mma, C=D accum
__device__ __forceinline__ void mma_tf32(float* c,
                                         uint32_t a0, uint32_t a1, uint32_t a2, uint32_t a3,
                                         uint32_t b0, uint32_t b1) {
    asm volatile(
        "mma.sync.aligned.m16n8k8.row.col.f32.tf32.tf32.f32 "
        "{%0,%1,%2,%3}, {%4,%5,%6,%7}, {%8,%9}, {%0,%1,%2,%3};"
        : "+f"(c[0]), "+f"(c[1]), "+f"(c[2]), "+f"(c[3])
        : "r"(a0), "r"(a1), "r"(a2), "r"(a3), "r"(b0), "r"(b1));
}

__device__ __forceinline__ float gelu_exact(float x) {
    return 0.5f * x * (1.0f + erff(x * 0.70710678118654752440f));
}

// ---------------- device scratch ----------------
__device__ __align__(16) float g_key[NC * KD];           // [cell][k]  (tf32-rounded)
__device__ __align__(16) float g_query[NG * KD];         // [gene][k]
__device__ __align__(16) float g_pnum[NSPLIT * ZD * NG]; // [split][z][gene]
__device__ __align__(16) float g_pden[NSPLIT * NG];      // [split][gene]
__device__ __align__(16) float g_densum[NG];

// ---------------- fused MLP prologue (key: blocks [0,256), query: rest) ----------------
#define KEY_BLOCKS (NC / 32)               // 256
#define QRY_BLOCKS ((NG + 63) / 64)        // 157
#define MLP_BLOCKS (KEY_BLOCKS + QRY_BLOCKS)

__global__ void __launch_bounds__(256, 1)
mlp_fused_kernel(const float* __restrict__ rawZ,
                 const float* __restrict__ Wz1, const float* __restrict__ bz1,
                 const float* __restrict__ Wz2, const float* __restrict__ bz2,
                 const float* __restrict__ Grep,
                 const float* __restrict__ Wg1, const float* __restrict__ bg1,
                 const float* __restrict__ Wg2, const float* __restrict__ bg2) {
    __shared__ float buf[ZD * 32 + 32 * HD];   // 11392 floats; query part aliases
    int tid = threadIdx.x;

    if (blockIdx.x < KEY_BLOCKS) {
        // ---- key MLP: 32 cells per block ----
        float* Zs = buf;                 // [k][cc] : 3200
        float* Hs = buf + ZD * 32;       // [cc][h] : 8192
        int c0 = blockIdx.x * 32;

        for (int idx = tid; idx < ZD * 32; idx += 256) {
            int k = idx >> 5, cc = idx & 31;
            Zs[idx] = rawZ[(size_t)k * NC + c0 + cc];
        }
        __syncthreads();
        {
            int h = tid;
            float w[ZD];
            #pragma unroll
            for (int k = 0; k < ZD; ++k) w[k] = Wz1[k * HD + h];
            float b = bz1[h];
            for (int cc = 0; cc < 32; ++cc) {
                float a = b;
                #pragma unroll
                for (int k = 0; k < ZD; ++k) a = fmaf(Zs[k * 32 + cc], w[k], a);
                Hs[cc * HD + h] = gelu_exact(a);
            }
        }
        __syncthreads();
        for (int idx = tid; idx < 32 * KD; idx += 256) {
            int cc = idx >> 5, kk = idx & 31;
            float a = bz2[kk];
            #pragma unroll 8
            for (int h = 0; h < HD; ++h) a = fmaf(Hs[cc * HD + h], Wz2[h * KD + kk], a);
            g_key[(size_t)(c0 + cc) * KD + kk] = to_tf32(a);
        }
    } else {
        // ---- query MLP: 64 genes per block ----
        float* Gq  = buf;                       // 64*101 = 6464
        float* W1s = buf + 64 * 101;            // 3200
        float* W2s = W1s + 100 * 32;            // 1024
        float* b1s = W2s + 32 * 32;             // 32
        float* b2s = b1s + 32;                  // 32
        int g0 = (blockIdx.x - KEY_BLOCKS) * 64;
        int valid = min(64, NG - g0);

        for (int idx = tid; idx < valid * 100; idx += 256) {
            int r = idx / 100, c = idx - r * 100;
            Gq[r * 101 + c] = Grep[(size_t)g0 * 100 + idx];
        }
        for (int idx = tid; idx < 100 * 32; idx += 256) W1s[idx] = Wg1[idx];
        for (int idx = tid; idx < 32 * 32; idx += 256) W2s[idx] = Wg2[idx];
        if (tid < 32) { b1s[tid] = bg1[tid]; b2s[tid] = bg2[tid]; }
        __syncthreads();

        if (tid < valid) {
            float hid[32];
            #pragma unroll
            for (int j = 0; j < 32; ++j) hid[j] = b1s[j];
            for (int k = 0; k < 100; ++k) {
                float gv = Gq[tid * 101 + k];
                #pragma unroll
                for (int j = 0; j < 32; ++j) hid[j] = fmaf(gv, W1s[k * 32 + j], hid[j]);
            }
            #pragma unroll
            for (int j = 0; j < 32; ++j) hid[j] = gelu_exact(hid[j]);
            int g = g0 + tid;
            #pragma unroll 4
            for (int kk = 0; kk < 32; ++kk) {
                float a = b2s[kk];
                #pragma unroll
                for (int j = 0; j < 32; ++j) a = fmaf(hid[j], W2s[j * 32 + kk], a);
                g_query[(size_t)g * KD + kk] = a;
            }
        }
    }
}

// ---------------- main fused kernel ----------------
// smem (floats)
#define KS_OFF 0
#define VBUF (104 * VSTR)                        // 7072 floats per V buffer
#define VS_OFF (CT * KSTR)                       // 2304
#define GS_OFF (VS_OFF + 2 * VBUF)               // 16448
#define PS_OFF (GS_OFF + GT * GSTR)              // 25152
#define SMEM_FLOATS (PS_OFF + GT * PSTR)         // 33856
#define SMEM_MAIN (SMEM_FLOATS * 4)              // 135424 B

__global__ void __launch_bounds__(THREADS, 1)
decoder_main_kernel(const float* __restrict__ gumbel,
                    const float* __restrict__ genZ) {
    extern __shared__ float smem[];
    float* Ks = smem + KS_OFF;
    float* Vs = smem + VS_OFF;   // [buf][z][cell]
    float* Gs = smem + GS_OFF;   // [gene][cell] raw gumbel
    float* Ps = smem + PS_OFF;   // [gene][cell]

    int tid = threadIdx.x;
    int wid = tid >> 5;
    int lane = tid & 31;
    int split = blockIdx.y;
    int gbase = blockIdx.x * GT;

    int lr = lane >> 2;
    int lc = lane & 3;

    // S identity: 2 warps per m-tile (8 m-tiles), each covers 4 n8 cell tiles
    int mS = wid & 7;
    int arowS = mS * 16 + lr;
    int ntS0 = (wid >> 3) * 4;      // nt in {ntS0 .. ntS0+3}

    // PV identity: warp = 1 m-tile (mg) x 1 n-group
    int mg = wid & 7;
    int ngrp = wid >> 3;
    int ntbase = ngrp * 7;
    int ntcnt = ngrp ? 6 : 7;

    // ldmatrix lane components
    int lt = lane >> 3, lrow = lane & 7;
    uint32_t ks_b = smem_u32(Ks);
    uint32_t vs_b = smem_u32(Vs);
    uint32_t gs_b = smem_u32(Gs);
    uint32_t ps_b = smem_u32(Ps);
    uint32_t k_lane = ks_b + (uint32_t)((lrow * KSTR + lt * 4) * 4);
    uint32_t a_lane = ps_b + (uint32_t)(((((lt & 1) * 8) + lrow) * PSTR + (lt >> 1) * 4) * 4);
    uint32_t aA0 = a_lane + (uint32_t)((mg * 16) * PSTR * 4);
    uint32_t b_lane0 = vs_b + (uint32_t)(((((lt >> 1) * 8) + lrow) * VSTR + (lt & 1) * 4) * 4);
    uint32_t b2_lane0 = vs_b + (uint32_t)((lrow * VSTR + (lt & 1) * 4) * 4)
                      + (uint32_t)(((ntbase + 6) * 8) * VSTR * 4);

    // staging lane assignments
    int kc = tid >> 3, kq = tid & 7;                 // K: 512 float4
    uint32_t k_dst = ks_b + (uint32_t)((kc * KSTR + kq * 4) * 4);

    // ---- Q fragments in registers, loaded once (tf32) ----
    uint32_t qf[4][4];
    {
        int gq0 = min(gbase + arowS, NG - 1);
        int gq1 = min(gbase + arowS + 8, NG - 1);
        const float* q0 = g_query + (size_t)gq0 * KD;
        const float* q1 = g_query + (size_t)gq1 * KD;
        #pragma unroll
        for (int k8 = 0; k8 < 4; ++k8) {
            int k = k8 * 8 + lc;
            qf[k8][0] = __float_as_uint(to_tf32(q0[k]));
            qf[k8][1] = __float_as_uint(to_tf32(q1[k]));
            qf[k8][2] = __float_as_uint(to_tf32(q0[k + 4]));
            qf[k8][3] = __float_as_uint(to_tf32(q1[k + 4]));
        }
    }

    // ---- staging helpers ----
    auto stage_K = [&](int cbase) {
        cpa16(k_dst, g_key + (size_t)(cbase + kc) * KD + kq * 4);
    };
    auto stage_V = [&](int buf, int cbase) {
        #pragma unroll
        for (int i = 0; i < 4; ++i) {
            int idx = tid + i * THREADS;
            if (idx < ZD * 16) {
                int z = idx >> 4, c4 = idx & 15;
                cpa16(vs_b + (uint32_t)((buf * VBUF + z * VSTR + c4 * 4) * 4),
                      genZ + (size_t)z * NC + cbase + c4 * 4);
            }
        }
    };
    auto stage_G = [&](int cbase) {
        #pragma unroll
        for (int i = 0; i < 4; ++i) {
            int idx = tid + i * THREADS;
            int gr = idx >> 4, c4 = idx & 15;
            int grow = min(gbase + gr, NG - 1);
            cpa16(gs_b + (uint32_t)((gr * GSTR + c4 * 4) * 4),
                  gumbel + (size_t)grow * NC + cbase + c4 * 4);
        }
    };

    float acc[7][4];
    #pragma unroll
    for (int i = 0; i < 7; ++i) {
        acc[i][0] = 0.f; acc[i][1] = 0.f;
        acc[i][2] = 0.f; acc[i][3] = 0.f;
    }

    // ---- prologue: stage chunk 0, fill V pad rows (both buffers, once) ----
    int cbase0 = split * CPC;
    stage_K(cbase0);
    stage_V(0, cbase0);
    stage_G(cbase0);
    CPA_COMMIT();
    if (tid < 128) {
        int buf = tid >> 6, zr = (tid >> 4) & 3, c4 = tid & 15;
        float4 v = (zr == 0) ? make_float4(1.f, 1.f, 1.f, 1.f)
                             : make_float4(0.f, 0.f, 0.f, 0.f);
        *reinterpret_cast<float4*>(Vs + buf * VBUF + (ZD + zr) * VSTR + c4 * 4) = v;
    }
    CPA_WAIT0();
    __syncthreads();

    for (int t = 0; t < NCHUNK; ++t) {
        int buf = t & 1;

        // ---- phase S: this warp's 4 cell tiles ----
        #pragma unroll
        for (int j = 0; j < 4; ++j) {
            int nt = ntS0 + j;
            uint32_t kb[8];
            uint32_t ka = k_lane + (uint32_t)(nt * 8 * KSTR * 4);
            ldmx4(kb, ka);
            ldmx4(kb + 4, ka + 64);
            float sacc[4] = {0.f, 0.f, 0.f, 0.f};
            mma_tf32(sacc, qf[0][0], qf[0][1], qf[0][2], qf[0][3], kb[0], kb[1]);
            mma_tf32(sacc, qf[1][0], qf[1][1], qf[1][2], qf[1][3], kb[2], kb[3]);
            mma_tf32(sacc, qf[2][0], qf[2][1], qf[2][2], qf[2][3], kb[4], kb[5]);
            mma_tf32(sacc, qf[3][0], qf[3][1], qf[3][2], qf[3][3], kb[6], kb[7]);
            int c0 = nt * 8 + 2 * lc;
            float2 gA = *reinterpret_cast<const float2*>(Gs + arowS * GSTR + c0);
            float2 gB = *reinterpret_cast<const float2*>(Gs + (arowS + 8) * GSTR + c0);
            float2 pA, pB;
            pA.x = exp2f(fmaf(gA.x, L2E, sacc[0] * SCALE_S));
            pA.y = exp2f(fmaf(gA.y, L2E, sacc[1] * SCALE_S));
            pB.x = exp2f(fmaf(gB.x, L2E, sacc[2] * SCALE_S));
            pB.y = exp2f(fmaf(gB.y, L2E, sacc[3] * SCALE_S));
            *reinterpret_cast<float2*>(Ps + arowS * PSTR + c0) = pA;
            *reinterpret_cast<float2*>(Ps + (arowS + 8) * PSTR + c0) = pB;
        }
        __syncthreads();   // Ps ready; Ks, Gs dead

        // ---- prefetch chunk t+1 into dead K/G and other V buffer ----
        if (t + 1 < NCHUNK) {
            int cb = split * CPC + (t + 1) * CT;
            stage_K(cb);
            stage_G(cb);
            stage_V(buf ^ 1, cb);
            CPA_COMMIT();
        }

        // ---- phase PV: D += P @ V_ext^T (reads Ps, Vs[buf]) ----
        uint32_t vbo = (uint32_t)(buf * VBUF * 4);
        #pragma unroll
        for (int k8 = 0; k8 < CT / 8; ++k8) {
            uint32_t k0b = (uint32_t)(k8 * 8 * 4);
            uint32_t af0[4];
            ldmx4(af0, aA0 + k0b);
            #pragma unroll
            for (int p = 0; p < 3; ++p) {
                uint32_t bf[4];
                ldmx4(bf, b_lane0 + vbo + (uint32_t)(((ntbase + 2 * p) * 8) * VSTR * 4) + k0b);
                mma_tf32(acc[2 * p],     af0[0], af0[1], af0[2], af0[3], bf[0], bf[1]);
                mma_tf32(acc[2 * p + 1], af0[0], af0[1], af0[2], af0[3], bf[2], bf[3]);
            }
            if (ngrp == 0) {
                uint32_t bf2[2];
                ldmx2(bf2, b2_lane0 + vbo + k0b);
                mma_tf32(acc[6], af0[0], af0[1], af0[2], af0[3], bf2[0], bf2[1]);
            }
        }
        if (t + 1 < NCHUNK) { CPA_WAIT0(); }
        __syncthreads();   // PV done (Ps/V dead); prefetched K/G/V visible
    }

    // ---- epilogue: scatter D fragments to split partials ----
    {
        float* pbase = g_pnum + (size_t)split * (ZD * NG);
        float* dbase = g_pden + split * NG;
        int gl = gbase + mg * 16 + lr;
        int gh = gl + 8;
        #pragma unroll
        for (int i = 0; i < 7; ++i) {
            if (i < ntcnt) {
                int nt = ntbase + i;
                int z0 = nt * 8 + 2 * lc;
                #pragma unroll
                for (int zz = 0; zz < 2; ++zz) {
                    int z = z0 + zz;
                    if (z < ZD) {
                        if (gl < NG) pbase[(size_t)z * NG + gl] = acc[i][zz];
                        if (gh < NG) pbase[(size_t)z * NG + gh] = acc[i][2 + zz];
                    } else if (z == ZD) {
                        if (gl < NG) dbase[gl] = acc[i][zz];
                        if (gh < NG) dbase[gh] = acc[i][2 + zz];
                    }
                }
            }
        }
    }
}

// ---------------- den pre-reduction ----------------
__global__ void densum_kernel() {
    int i4 = blockIdx.x * blockDim.x + threadIdx.x;
    int base = i4 * 4;
    if (base >= NG) return;
    float4 d = make_float4(0.f, 0.f, 0.f, 0.f);
    #pragma unroll
    for (int s = 0; s < NSPLIT; ++s) {
        float4 x = *reinterpret_cast<const float4*>(g_pden + s * NG + base);
        d.x += x.x; d.y += x.y; d.z += x.z; d.w += x.w;
    }
    *reinterpret_cast<float4*>(g_densum + base) = d;
}

// ---------------- reduce: sum num splits, divide by densum (2 float4/thread) ----------------
__global__ void reduce_kernel(float* __restrict__ out) {
    int i8 = blockIdx.x * blockDim.x + threadIdx.x;
    int base = i8 * 8;
    if (base >= ZD * NG) return;
    int gidx = base % NG;   // NG % 8 == 0 -> both float4s in same gene row
    float4 n0 = make_float4(0.f, 0.f, 0.f, 0.f);
    float4 n1 = make_float4(0.f, 0.f, 0.f, 0.f);
    #pragma unroll
    for (int s = 0; s < NSPLIT; ++s) {
        const float* p = g_pnum + (size_t)s * (ZD * NG) + base;
        float4 a = *reinterpret_cast<const float4*>(p);
        float4 b = *reinterpret_cast<const float4*>(p + 4);
        n0.x += a.x; n0.y += a.y; n0.z += a.z; n0.w += a.w;
        n1.x += b.x; n1.y += b.y; n1.z += b.z; n1.w += b.w;
    }
    float4 d0 = *reinterpret_cast<const float4*>(g_densum + gidx);
    float4 d1 = *reinterpret_cast<const float4*>(g_densum + gidx + 4);
    float4 o0, o1;
    o0.x = n0.x / d0.x; o0.y = n0.y / d0.y; o0.z = n0.z / d0.z; o0.w = n0.w / d0.w;
    o1.x = n1.x / d1.x; o1.y = n1.y / d1.y; o1.z = n1.z / d1.z; o1.w = n1.w / d1.w;
    *reinterpret_cast<float4*>(out + base) = o0;
    *reinterpret_cast<float4*>(out + base + 4) = o1;
}

// ---------------- launch ----------------
extern "C" void kernel_launch(void* const* d_in, const int* in_sizes, int n_in,
                              void* d_out, int out_size) {
    const float* rawZ   = (const float*)d_in[0];
    const float* genZ   = (const float*)d_in[1];
    const float* Grep   = (const float*)d_in[2];
    const float* gumbel = (const float*)d_in[3];
    const float* Wz1 = (const float*)d_in[4];
    const float* bz1 = (const float*)d_in[5];
    const float* Wz2 = (const float*)d_in[6];
    const float* bz2 = (const float*)d_in[7];
    const float* Wg1 = (const float*)d_in[8];
    const float* bg1 = (const float*)d_in[9];
    const float* Wg2 = (const float*)d_in[10];
    const float* bg2 = (const float*)d_in[11];
    float* out = (float*)d_out;

    cudaFuncSetAttribute(decoder_main_kernel,
                         cudaFuncAttributeMaxDynamicSharedMemorySize, SMEM_MAIN);

    mlp_fused_kernel<<<MLP_BLOCKS, 256>>>(rawZ, Wz1, bz1, Wz2, bz2,
                                          Grep, Wg1, bg1, Wg2, bg2);

    dim3 grid((NG + GT - 1) / GT, NSPLIT);
    decoder_main_kernel<<<grid, THREADS, SMEM_MAIN>>>(gumbel, genZ);

    densum_kernel<<<(NG / 4 + 255) / 256, 256>>>();
    reduce_kernel<<<(ZD * NG / 8 + 255) / 256, 256>>>(out);
}

// round 12
// speedup vs baseline: 4.0200x; 1.1282x over previous
#include <cuda_runtime.h>
#include <math.h>
#include <stdint.h>

#define NG 10000      // genes
#define NC 8192       // cells
#define ZD 100        // z dim
#define KD 32         // key dim
#define HD 256        // hidden dim (key MLP)
#define GT 128        // genes per CTA (= M)
#define CT 64         // cells per chunk
#define NSPLIT 16     // cell splits
#define CPC (NC / NSPLIT)        // 512 cells per CTA
#define NCHUNK (CPC / CT)        // 8 chunks
#define THREADS 256

#define KSTR 36       // Ks row stride (floats)
#define VSTR 68       // Vs row stride (z-major: [z][cell])
#define GSTR 68       // Gs row stride
#define PSTR 68       // Ps row stride

// log2(e), log2(e)/sqrt(32)
#define L2E 1.4426950408889634f
#define SCALE_S 0.25503482f

typedef unsigned long long u64;

__device__ __forceinline__ uint32_t smem_u32(const void* p) {
    uint32_t a;
    asm("{ .reg .u64 t; cvta.to.shared.u64 t, %1; cvt.u32.u64 %0, t; }" : "=r"(a) : "l"(p));
    return a;
}

__device__ __forceinline__ float to_tf32(float x) {
    uint32_t r;
    asm("cvt.rna.tf32.f32 %0, %1;" : "=r"(r) : "f"(x));
    return __uint_as_float(r);
}

__device__ __forceinline__ void cpa16(uint32_t dst, const void* src) {
    asm volatile("cp.async.cg.shared.global [%0], [%1], 16;" :: "r"(dst), "l"(src));
}
#define CPA_COMMIT() asm volatile("cp.async.commit_group;" ::: "memory")
#define CPA_WAIT0()  asm volatile("cp.async.wait_group 0;" ::: "memory")
#define CPA_WAIT1()  asm volatile("cp.async.wait_group 1;" ::: "memory")

__device__ __forceinline__ void ldmx4(uint32_t* r, uint32_t addr) {
    asm volatile("ldmatrix.sync.aligned.m8n8.x4.shared.b16 {%0,%1,%2,%3}, [%4];"
        : "=r"(r[0]), "=r"(r[1]), "=r"(r[2]), "=r"(r[3]) : "r"(addr));
}
__device__ __forceinline__ void ldmx2(uint32_t* r, uint32_t addr) {
    asm volatile("ldmatrix.sync.aligned.m8n8.x2.shared.b16 {%0,%1}, [%2];"
        : "=r"(r[0]), "=r"(r[1]) : "r"(addr));
}

// m16n8k8 tf32 mma, C=D accum
__device__ __forceinline__ void mma_tf32(float* c,
                                         uint32_t a0, uint32_t a1, uint32_t a2, uint32_t a3,
                                         uint32_t b0, uint32_t b1) {
    asm volatile(
        "mma.sync.aligned.m16n8k8.row.col.f32.tf32.tf32.f32 "
        "{%0,%1,%2,%3}, {%4,%5,%6,%7}, {%8,%9}, {%0,%1,%2,%3};"
        : "+f"(c[0]), "+f"(c[1]), "+f"(c[2]), "+f"(c[3])
        : "r"(a0), "r"(a1), "r"(a2), "r"(a3), "r"(b0), "r"(b1));
}

__device__ __forceinline__ float gelu_exact(float x) {
    return 0.5f * x * (1.0f + erff(x * 0.70710678118654752440f));
}

// ---------------- device scratch ----------------
__device__ __align__(16) float g_key[NC * KD];           // [cell][k]  (tf32-rounded)
__device__ __align__(16) float g_query[NG * KD];         // [gene][k]
__device__ __align__(16) float g_pnum[NSPLIT * ZD * NG]; // [split][z][gene]
__device__ __align__(16) float g_pden[NSPLIT * NG];      // [split][gene]
__device__ __align__(16) float g_densum[NG];

// ---------------- fused MLP prologue (key: blocks [0,256), query: rest) ----------------
#define KEY_BLOCKS (NC / 32)               // 256
#define QRY_BLOCKS ((NG + 63) / 64)        // 157
#define MLP_BLOCKS (KEY_BLOCKS + QRY_BLOCKS)

__global__ void __launch_bounds__(256, 1)
mlp_fused_kernel(const float* __restrict__ rawZ,
                 const float* __restrict__ Wz1, const float* __restrict__ bz1,
                 const float* __restrict__ Wz2, const float* __restrict__ bz2,
                 const float* __restrict__ Grep,
                 const float* __restrict__ Wg1, const float* __restrict__ bg1,
                 const float* __restrict__ Wg2, const float* __restrict__ bg2) {
    __shared__ float buf[ZD * 32 + 32 * HD];   // 11392 floats; query part aliases
    int tid = threadIdx.x;

    if (blockIdx.x < KEY_BLOCKS) {
        // ---- key MLP: 32 cells per block ----
        float* Zs = buf;                 // [k][cc]
        float* Hs = buf + ZD * 32;       // [cc][h]
        int c0 = blockIdx.x * 32;

        for (int idx = tid; idx < ZD * 32; idx += 256) {
            int k = idx >> 5, cc = idx & 31;
            Zs[idx] = rawZ[(size_t)k * NC + c0 + cc];
        }
        __syncthreads();
        {
            int h = tid;
            float w[ZD];
            #pragma unroll
            for (int k = 0; k < ZD; ++k) w[k] = Wz1[k * HD + h];
            float b = bz1[h];
            for (int cc = 0; cc < 32; ++cc) {
                float a = b;
                #pragma unroll
                for (int k = 0; k < ZD; ++k) a = fmaf(Zs[k * 32 + cc], w[k], a);
                Hs[cc * HD + h] = gelu_exact(a);
            }
        }
        __syncthreads();
        for (int idx = tid; idx < 32 * KD; idx += 256) {
            int cc = idx >> 5, kk = idx & 31;
            float a = bz2[kk];
            #pragma unroll 8
            for (int h = 0; h < HD; ++h) a = fmaf(Hs[cc * HD + h], Wz2[h * KD + kk], a);
            g_key[(size_t)(c0 + cc) * KD + kk] = to_tf32(a);
        }
    } else {
        // ---- query MLP: 64 genes per block ----
        float* Gq  = buf;
        float* W1s = buf + 64 * 101;
        float* W2s = W1s + 100 * 32;
        float* b1s = W2s + 32 * 32;
        float* b2s = b1s + 32;
        int g0 = (blockIdx.x - KEY_BLOCKS) * 64;
        int valid = min(64, NG - g0);

        for (int idx = tid; idx < valid * 100; idx += 256) {
            int r = idx / 100, c = idx - r * 100;
            Gq[r * 101 + c] = Grep[(size_t)g0 * 100 + idx];
        }
        for (int idx = tid; idx < 100 * 32; idx += 256) W1s[idx] = Wg1[idx];
        for (int idx = tid; idx < 32 * 32; idx += 256) W2s[idx] = Wg2[idx];
        if (tid < 32) { b1s[tid] = bg1[tid]; b2s[tid] = bg2[tid]; }
        __syncthreads();

        if (tid < valid) {
            float hid[32];
            #pragma unroll
            for (int j = 0; j < 32; ++j) hid[j] = b1s[j];
            for (int k = 0; k < 100; ++k) {
                float gv = Gq[tid * 101 + k];
                #pragma unroll
                for (int j = 0; j < 32; ++j) hid[j] = fmaf(gv, W1s[k * 32 + j], hid[j]);
            }
            #pragma unroll
            for (int j = 0; j < 32; ++j) hid[j] = gelu_exact(hid[j]);
            int g = g0 + tid;
            #pragma unroll 4
            for (int kk = 0; kk < 32; ++kk) {
                float a = b2s[kk];
                #pragma unroll
                for (int j = 0; j < 32; ++j) a = fmaf(hid[j], W2s[j * 32 + kk], a);
                g_query[(size_t)g * KD + kk] = a;
            }
        }
    }
}

// ---------------- main fused kernel ----------------
// smem (floats), single V buffer
#define KS_OFF 0
#define VS_OFF (CT * KSTR)                       // 2304
#define GS_OFF (VS_OFF + 104 * VSTR)             // 9376
#define PS_OFF (GS_OFF + GT * GSTR)              // 18080
#define SMEM_FLOATS (PS_OFF + GT * PSTR)         // 26784
#define SMEM_MAIN (SMEM_FLOATS * 4)              // 107136 B -> 2 CTAs/SM

__global__ void __launch_bounds__(THREADS, 2)
decoder_main_kernel(const float* __restrict__ gumbel,
                    const float* __restrict__ genZ) {
    extern __shared__ float smem[];
    float* Ks = smem + KS_OFF;
    float* Vs = smem + VS_OFF;   // [z][cell]
    float* Gs = smem + GS_OFF;   // [gene][cell] raw gumbel
    float* Ps = smem + PS_OFF;   // [gene][cell]

    int tid = threadIdx.x;
    int wid = tid >> 5;          // 0..7 = m-tile
    int lane = tid & 31;
    int split = blockIdx.y;
    int gbase = blockIdx.x * GT;

    int lr = lane >> 2;
    int lc = lane & 3;
    int arowS = wid * 16 + lr;   // m-tile row for S and PV

    // ldmatrix lane components
    int lt = lane >> 3, lrow = lane & 7;
    uint32_t ks_b = smem_u32(Ks);
    uint32_t vs_b = smem_u32(Vs);
    uint32_t gs_b = smem_u32(Gs);
    uint32_t ps_b = smem_u32(Ps);
    uint32_t k_lane = ks_b + (uint32_t)((lrow * KSTR + lt * 4) * 4);
    uint32_t a_lane = ps_b + (uint32_t)(((((lt & 1) * 8) + lrow) * PSTR + (lt >> 1) * 4) * 4)
                    + (uint32_t)((wid * 16) * PSTR * 4);
    uint32_t b_lane = vs_b + (uint32_t)(((((lt >> 1) * 8) + lrow) * VSTR + (lt & 1) * 4) * 4);
    uint32_t b2_lane = vs_b + (uint32_t)((lrow * VSTR + (lt & 1) * 4) * 4)
                     + (uint32_t)((12 * 8) * VSTR * 4);

    // staging lane assignment for K (512 float4, 2 per thread)
    // ---- Q fragments in registers, loaded once (tf32) ----
    uint32_t qf[4][4];
    {
        int gq0 = min(gbase + arowS, NG - 1);
        int gq1 = min(gbase + arowS + 8, NG - 1);
        const float* q0 = g_query + (size_t)gq0 * KD;
        const float* q1 = g_query + (size_t)gq1 * KD;
        #pragma unroll
        for (int k8 = 0; k8 < 4; ++k8) {
            int k = k8 * 8 + lc;
            qf[k8][0] = __float_as_uint(to_tf32(q0[k]));
            qf[k8][1] = __float_as_uint(to_tf32(q1[k]));
            qf[k8][2] = __float_as_uint(to_tf32(q0[k + 4]));
            qf[k8][3] = __float_as_uint(to_tf32(q1[k + 4]));
        }
    }

    // ---- staging helpers ----
    auto stage_K = [&](int cbase) {
        #pragma unroll
        for (int i = 0; i < 2; ++i) {
            int idx = tid + i * THREADS;
            int kc = idx >> 3, kq = idx & 7;
            cpa16(ks_b + (uint32_t)((kc * KSTR + kq * 4) * 4),
                  g_key + (size_t)(cbase + kc) * KD + kq * 4);
        }
    };
    auto stage_V = [&](int cbase) {
        #pragma unroll
        for (int i = 0; i < 7; ++i) {
            int idx = tid + i * THREADS;
            if (idx < ZD * 16) {
                int z = idx >> 4, c4 = idx & 15;
                cpa16(vs_b + (uint32_t)((z * VSTR + c4 * 4) * 4),
                      genZ + (size_t)z * NC + cbase + c4 * 4);
            }
        }
    };
    auto stage_G = [&](int cbase) {
        #pragma unroll
        for (int i = 0; i < 8; ++i) {
            int idx = tid + i * THREADS;
            int gr = idx >> 4, c4 = idx & 15;
            int grow = min(gbase + gr, NG - 1);
            cpa16(gs_b + (uint32_t)((gr * GSTR + c4 * 4) * 4),
                  gumbel + (size_t)grow * NC + cbase + c4 * 4);
        }
    };

    float acc[13][4];
    #pragma unroll
    for (int i = 0; i < 13; ++i) {
        acc[i][0] = 0.f; acc[i][1] = 0.f;
        acc[i][2] = 0.f; acc[i][3] = 0.f;
    }

    // ---- prologue: stage chunk 0; fill V pad rows once ----
    int cbase0 = split * CPC;
    stage_K(cbase0);
    stage_V(cbase0);
    stage_G(cbase0);
    CPA_COMMIT();
    if (tid < 64) {
        int zr = tid >> 4, c4 = tid & 15;   // z = 100..103
        float4 v = (zr == 0) ? make_float4(1.f, 1.f, 1.f, 1.f)
                             : make_float4(0.f, 0.f, 0.f, 0.f);
        *reinterpret_cast<float4*>(Vs + (ZD + zr) * VSTR + c4 * 4) = v;
    }
    CPA_WAIT0();
    __syncthreads();

    for (int t = 0; t < NCHUNK; ++t) {
        // ---- phase S: this warp's m-tile x 8 cell tiles ----
        #pragma unroll
        for (int nt = 0; nt < CT / 8; ++nt) {
            uint32_t kb[8];
            uint32_t ka = k_lane + (uint32_t)(nt * 8 * KSTR * 4);
            ldmx4(kb, ka);
            ldmx4(kb + 4, ka + 64);
            float sacc[4] = {0.f, 0.f, 0.f, 0.f};
            mma_tf32(sacc, qf[0][0], qf[0][1], qf[0][2], qf[0][3], kb[0], kb[1]);
            mma_tf32(sacc, qf[1][0], qf[1][1], qf[1][2], qf[1][3], kb[2], kb[3]);
            mma_tf32(sacc, qf[2][0], qf[2][1], qf[2][2], qf[2][3], kb[4], kb[5]);
            mma_tf32(sacc, qf[3][0], qf[3][1], qf[3][2], qf[3][3], kb[6], kb[7]);
            int c0 = nt * 8 + 2 * lc;
            float2 gA = *reinterpret_cast<const float2*>(Gs + arowS * GSTR + c0);
            float2 gB = *reinterpret_cast<const float2*>(Gs + (arowS + 8) * GSTR + c0);
            float2 pA, pB;
            pA.x = exp2f(fmaf(gA.x, L2E, sacc[0] * SCALE_S));
            pA.y = exp2f(fmaf(gA.y, L2E, sacc[1] * SCALE_S));
            pB.x = exp2f(fmaf(gB.x, L2E, sacc[2] * SCALE_S));
            pB.y = exp2f(fmaf(gB.y, L2E, sacc[3] * SCALE_S));
            *reinterpret_cast<float2*>(Ps + arowS * PSTR + c0) = pA;
            *reinterpret_cast<float2*>(Ps + (arowS + 8) * PSTR + c0) = pB;
        }
        __syncthreads();   // Ps ready; Ks, Gs dead

        // ---- prefetch K/G of chunk t+1 into dead buffers ----
        if (t + 1 < NCHUNK) {
            int cb = split * CPC + (t + 1) * CT;
            stage_K(cb);
            stage_G(cb);
            CPA_COMMIT();
            CPA_WAIT1();   // retire V(t) (committed before KG(t+1)); KG may stay in flight
        } else {
            CPA_WAIT0();   // last chunk: make sure V(t) complete
        }

        // ---- phase PV: D += P @ V_ext^T (13 n-tiles) ----
        #pragma unroll
        for (int k8 = 0; k8 < CT / 8; ++k8) {
            uint32_t k0b = (uint32_t)(k8 * 8 * 4);
            uint32_t af0[4];
            ldmx4(af0, a_lane + k0b);
            #pragma unroll
            for (int p = 0; p < 6; ++p) {
                uint32_t bf[4];
                ldmx4(bf, b_lane + (uint32_t)((2 * p * 8) * VSTR * 4) + k0b);
                mma_tf32(acc[2 * p],     af0[0], af0[1], af0[2], af0[3], bf[0], bf[1]);
                mma_tf32(acc[2 * p + 1], af0[0], af0[1], af0[2], af0[3], bf[2], bf[3]);
            }
            {
                uint32_t bf2[2];
                ldmx2(bf2, b2_lane + k0b);
                mma_tf32(acc[12], af0[0], af0[1], af0[2], af0[3], bf2[0], bf2[1]);
            }
        }
        if (t + 1 < NCHUNK) { CPA_WAIT0(); }   // KG(t+1) complete
        __syncthreads();   // PV done; Ps/Vs dead; KG(t+1) visible

        // ---- stage V of chunk t+1 (own group; completes during next S) ----
        if (t + 1 < NCHUNK) {
            stage_V(split * CPC + (t + 1) * CT);
            CPA_COMMIT();
        }
    }

    // ---- epilogue: scatter D fragments to split partials ----
    {
        float* pbase = g_pnum + (size_t)split * (ZD * NG);
        float* dbase = g_pden + split * NG;
        int gl = gbase + wid * 16 + lr;
        int gh = gl + 8;
        #pragma unroll
        for (int nt = 0; nt < 13; ++nt) {
            int z0 = nt * 8 + 2 * lc;
            #pragma unroll
            for (int zz = 0; zz < 2; ++zz) {
                int z = z0 + zz;
                if (z < ZD) {
                    if (gl < NG) pbase[(size_t)z * NG + gl] = acc[nt][zz];
                    if (gh < NG) pbase[(size_t)z * NG + gh] = acc[nt][2 + zz];
                } else if (z == ZD) {
                    if (gl < NG) dbase[gl] = acc[nt][zz];
                    if (gh < NG) dbase[gh] = acc[nt][2 + zz];
                }
            }
        }
    }
}

// ---------------- den pre-reduction ----------------
__global__ void densum_kernel() {
    int i4 = blockIdx.x * blockDim.x + threadIdx.x;
    int base = i4 * 4;
    if (base >= NG) return;
    float4 d = make_float4(0.f, 0.f, 0.f, 0.f);
    #pragma unroll
    for (int s = 0; s < NSPLIT; ++s) {
        float4 x = *reinterpret_cast<const float4*>(g_pden + s * NG + base);
        d.x += x.x; d.y += x.y; d.z += x.z; d.w += x.w;
    }
    *reinterpret_cast<float4*>(g_densum + base) = d;
}

// ---------------- reduce: sum num splits, divide by densum (2 float4/thread) ----------------
__global__ void reduce_kernel(float* __restrict__ out) {
    int i8 = blockIdx.x * blockDim.x + threadIdx.x;
    int base = i8 * 8;
    if (base >= ZD * NG) return;
    int gidx = base % NG;
    float4 n0 = make_float4(0.f, 0.f, 0.f, 0.f);
    float4 n1 = make_float4(0.f, 0.f, 0.f, 0.f);
    #pragma unroll
    for (int s = 0; s < NSPLIT; ++s) {
        const float* p = g_pnum + (size_t)s * (ZD * NG) + base;
        float4 a = *reinterpret_cast<const float4*>(p);
        float4 b = *reinterpret_cast<const float4*>(p + 4);
        n0.x += a.x; n0.y += a.y; n0.z += a.z; n0.w += a.w;
        n1.x += b.x; n1.y += b.y; n1.z += b.z; n1.w += b.w;
    }
    float4 d0 = *reinterpret_cast<const float4*>(g_densum + gidx);
    float4 d1 = *reinterpret_cast<const float4*>(g_densum + gidx + 4);
    float4 o0, o1;
    o0.x = n0.x / d0.x; o0.y = n0.y / d0.y; o0.z = n0.z / d0.z; o0.w = n0.w / d0.w;
    o1.x = n1.x / d1.x; o1.y = n1.y / d1.y; o1.z = n1.z / d1.z; o1.w = n1.w / d1.w;
    *reinterpret_cast<float4*>(out + base) = o0;
    *reinterpret_cast<float4*>(out + base + 4) = o1;
}

// ---------------- launch ----------------
extern "C" void kernel_launch(void* const* d_in, const int* in_sizes, int n_in,
                              void* d_out, int out_size) {
    const float* rawZ   = (const float*)d_in[0];
    const float* genZ   = (const float*)d_in[1];
    const float* Grep   = (const float*)d_in[2];
    const float* gumbel = (const float*)d_in[3];
    const float* Wz1 = (const float*)d_in[4];
    const float* bz1 = (const float*)d_in[5];
    const float* Wz2 = (const float*)d_in[6];
    const float* bz2 = (const float*)d_in[7];
    const float* Wg1 = (const float*)d_in[8];
    const float* bg1 = (const float*)d_in[9];
    const float* Wg2 = (const float*)d_in[10];
    const float* bg2 = (const float*)d_in[11];
    float* out = (float*)d_out;

    cudaFuncSetAttribute(decoder_main_kernel,
                         cudaFuncAttributeMaxDynamicSharedMemorySize, SMEM_MAIN);

    mlp_fused_kernel<<<MLP_BLOCKS, 256>>>(rawZ, Wz1, bz1, Wz2, bz2,
                                          Grep, Wg1, bg1, Wg2, bg2);

    dim3 grid((NG + GT - 1) / GT, NSPLIT);
    decoder_main_kernel<<<grid, THREADS, SMEM_MAIN>>>(gumbel, genZ);

    densum_kernel<<<(NG / 4 + 255) / 256, 256>>>();
    reduce_kernel<<<(ZD * NG / 8 + 255) / 256, 256>>>(out);
}